// round 10
// baseline (speedup 1.0000x reference)
#include <cuda_runtime.h>
#include <cuda_bf16.h>
#include <cuda_fp16.h>
#include <math.h>
#include <cstdint>

// ---------------------------------------------------------------------------
// GCN: 3x { H = A_sparse @ (H @ W) + b (,ReLU) } -> log_softmax
// N=50000, E=1.6M, 512 -> 128 -> 128 -> 40
// Round 10: SpMM fused INTO the following GEMM (aggregation writes bf16 hi/lo
//           straight into A smem tiles). Post-join: 3 kernels total.
// ---------------------------------------------------------------------------

#define NNODES 50000
#define NEDGES 1600000
#define NFEAT 512
#define NHID  128
#define NCLASS 40

// Scratch (__device__ globals; no allocations allowed)
__device__ __half g_Ah[NNODES * NHID];   // GEMM1 output (layer-1 pre-agg)
__device__ __half g_Bh[NNODES * NHID];   // fused128 output (layer-2 pre-agg)
__device__ __half g_Ch[NNODES * NCLASS]; // fused40 output (fp16 logits)
__device__ int    g_cnt[NNODES];
__device__ int    g_cursor[NNODES];
__device__ int    g_rp[NNODES + 1];
__device__ int    g_tmp[NNODES];
__device__ int    g_bsum[256];
__device__ int2   g_pe[NEDGES];          // packed (src, weight-bits)
// Pre-packed weights: bf16x2 k-pairs
__device__ uint32_t g_W1h[256 * 128];
__device__ uint32_t g_W1l[256 * 128];
__device__ uint32_t g_Whh[64 * 128];
__device__ uint32_t g_Whl[64 * 128];
__device__ uint32_t g_W2h[64 * 40];
__device__ uint32_t g_W2l[64 * 40];

// ===========================================================================
// helpers
// ===========================================================================
__device__ __forceinline__ void cvt_hilo(float x, float y, uint32_t& hi, uint32_t& lo) {
    __nv_bfloat16 hx = __float2bfloat16(x);
    __nv_bfloat16 hy = __float2bfloat16(y);
    float rx = x - __bfloat162float(hx);
    float ry = y - __bfloat162float(hy);
    __nv_bfloat162 H; H.x = hx; H.y = hy;
    __nv_bfloat162 L; L.x = __float2bfloat16(rx); L.y = __float2bfloat16(ry);
    hi = *reinterpret_cast<uint32_t*>(&H);
    lo = *reinterpret_cast<uint32_t*>(&L);
}

__device__ __forceinline__ void mma16816(float* d, const uint32_t* a, uint32_t b0, uint32_t b1) {
    asm volatile(
        "mma.sync.aligned.m16n8k16.row.col.f32.bf16.bf16.f32 "
        "{%0,%1,%2,%3}, {%4,%5,%6,%7}, {%8,%9}, {%0,%1,%2,%3};"
        : "+f"(d[0]), "+f"(d[1]), "+f"(d[2]), "+f"(d[3])
        : "r"(a[0]), "r"(a[1]), "r"(a[2]), "r"(a[3]), "r"(b0), "r"(b1));
}

// SMEM layout (u32 units) for K=64 chunk tiles.
#define AH_OFF 0
#define AL_OFF 4608
#define BH_OFF 9216
#define BL_OFF 13568
#define SM_U32 17920        // 71680 bytes (fused128 / gemm1)
// fused40: A tiles same, B tiles [32][44]
#define B40H_OFF 9216
#define B40L_OFF 10624
#define SM40_U32 12032      // 48128 bytes

// ===========================================================================
// Weight pre-pack: fp32 -> hi/lo bf16x2 planes
// ===========================================================================
__global__ void conv_weights(const float* __restrict__ W1, const float* __restrict__ Wh,
                             const float* __restrict__ W2,
                             uint32_t* __restrict__ W1h, uint32_t* __restrict__ W1l,
                             uint32_t* __restrict__ Whh, uint32_t* __restrict__ Whl,
                             uint32_t* __restrict__ W2h, uint32_t* __restrict__ W2l) {
    int i = blockIdx.x * 256 + threadIdx.x;
    if (i < 256 * 128) {
        int k2 = i >> 7, n = i & 127;
        float v0 = __ldg(W1 + (size_t)(2 * k2) * 128 + n);
        float v1 = __ldg(W1 + (size_t)(2 * k2 + 1) * 128 + n);
        uint32_t h, lo;
        cvt_hilo(v0, v1, h, lo);
        W1h[i] = h; W1l[i] = lo;
    } else if (i < 256 * 128 + 64 * 128) {
        int j = i - 256 * 128;
        int k2 = j >> 7, n = j & 127;
        float v0 = __ldg(Wh + (size_t)(2 * k2) * 128 + n);
        float v1 = __ldg(Wh + (size_t)(2 * k2 + 1) * 128 + n);
        uint32_t h, lo;
        cvt_hilo(v0, v1, h, lo);
        Whh[j] = h; Whl[j] = lo;
    } else if (i < 256 * 128 + 64 * 128 + 64 * 40) {
        int j = i - (256 * 128 + 64 * 128);
        int k2 = j / 40, n = j % 40;
        float v0 = __ldg(W2 + (size_t)(2 * k2) * 40 + n);
        float v1 = __ldg(W2 + (size_t)(2 * k2 + 1) * 40 + n);
        uint32_t h, lo;
        cvt_hilo(v0, v1, h, lo);
        W2h[j] = h; W2l[j] = lo;
    }
}

// ===========================================================================
// GEMM1: C[M,128] = x[M,512] @ W1; x fp32; W pre-packed; fp16 out.
// ===========================================================================
__global__ void __launch_bounds__(256, 2) mma_gemm128(
    const float* __restrict__ A,
    const uint32_t* __restrict__ Wph, const uint32_t* __restrict__ Wpl,
    __half* __restrict__ C, int M, int K) {
    extern __shared__ uint32_t sm[];
    uint32_t* AH = sm + AH_OFF;
    uint32_t* AL = sm + AL_OFF;
    uint32_t* BH = sm + BH_OFF;
    uint32_t* BL = sm + BL_OFF;

    const int t = threadIdx.x;
    const int lane = t & 31;
    const int wid = t >> 5;
    const int warpM = wid >> 1;
    const int warpN = wid & 1;
    const int row0 = blockIdx.x * 128;

    float acc[2][8][4];
#pragma unroll
    for (int mt = 0; mt < 2; mt++)
#pragma unroll
        for (int nt = 0; nt < 8; nt++)
#pragma unroll
            for (int e = 0; e < 4; e++) acc[mt][nt][e] = 0.f;

    const int r4 = lane >> 2;
    const int q4 = lane & 3;

    const int nChunks = K >> 6;
    for (int c = 0; c < nChunks; c++) {
        const int k0 = c << 6;
        const int k0h = c << 5;
        __syncthreads();

#pragma unroll
        for (int l = 0; l < 8; l++) {
            int q = t + l * 256;
            int m = q >> 4;
            int c4 = q & 15;
            float4 v = make_float4(0.f, 0.f, 0.f, 0.f);
            if (row0 + m < M)
                v = *reinterpret_cast<const float4*>(A + (size_t)(row0 + m) * K + k0 + c4 * 4);
            uint32_t h0, l0, h1, l1;
            cvt_hilo(v.x, v.y, h0, l0);
            cvt_hilo(v.z, v.w, h1, l1);
            int base = m * 36 + c4 * 2;
            AH[base] = h0; AH[base + 1] = h1;
            AL[base] = l0; AL[base + 1] = l1;
        }
#pragma unroll
        for (int l = 0; l < 4; l++) {
            int q = t + l * 256;
            int k2 = q >> 5;
            int n4 = q & 31;
            size_t goff = (size_t)(k0h + k2) * 128 + n4 * 4;
            uint4 vh = __ldg(reinterpret_cast<const uint4*>(Wph + goff));
            uint4 vl = __ldg(reinterpret_cast<const uint4*>(Wpl + goff));
            *reinterpret_cast<uint4*>(&BH[k2 * 136 + n4 * 4]) = vh;
            *reinterpret_cast<uint4*>(&BL[k2 * 136 + n4 * 4]) = vl;
        }
        __syncthreads();

#pragma unroll
        for (int k8 = 0; k8 < 4; k8++) {
            int klo = k8 * 8 + q4;
            uint32_t ah[2][4], al[2][4];
#pragma unroll
            for (int mt = 0; mt < 2; mt++) {
                int base = (warpM * 32 + mt * 16 + r4) * 36;
                ah[mt][0] = AH[base + klo];
                ah[mt][1] = AH[base + 8 * 36 + klo];
                ah[mt][2] = AH[base + klo + 4];
                ah[mt][3] = AH[base + 8 * 36 + klo + 4];
                al[mt][0] = AL[base + klo];
                al[mt][1] = AL[base + 8 * 36 + klo];
                al[mt][2] = AL[base + klo + 4];
                al[mt][3] = AL[base + 8 * 36 + klo + 4];
            }
#pragma unroll
            for (int nt = 0; nt < 8; nt++) {
                int nB = warpN * 64 + nt * 8 + r4;
                uint32_t bh0 = BH[klo * 136 + nB];
                uint32_t bh1 = BH[(klo + 4) * 136 + nB];
                uint32_t bl0 = BL[klo * 136 + nB];
                uint32_t bl1 = BL[(klo + 4) * 136 + nB];
#pragma unroll
                for (int mt = 0; mt < 2; mt++) {
                    mma16816(acc[mt][nt], ah[mt], bh0, bh1);
                    mma16816(acc[mt][nt], ah[mt], bl0, bl1);
                    mma16816(acc[mt][nt], al[mt], bh0, bh1);
                }
            }
        }
    }

#pragma unroll
    for (int mt = 0; mt < 2; mt++) {
        int rowA = row0 + warpM * 32 + mt * 16 + r4;
        int rowB = rowA + 8;
#pragma unroll
        for (int nt = 0; nt < 8; nt++) {
            int col = warpN * 64 + nt * 8 + q4 * 2;
            if (rowA < M)
                *reinterpret_cast<__half2*>(C + (size_t)rowA * 128 + col) =
                    __floats2half2_rn(acc[mt][nt][0], acc[mt][nt][1]);
            if (rowB < M)
                *reinterpret_cast<__half2*>(C + (size_t)rowB * 128 + col) =
                    __floats2half2_rn(acc[mt][nt][2], acc[mt][nt][3]);
        }
    }
}

// ===========================================================================
// Aggregation helper: per-lane 2 feats (half2), fp32 accumulate
// ===========================================================================
__device__ __forceinline__ void agg2(float& ax, float& ay, float w, uint32_t h) {
    float2 v = __half22float2(*reinterpret_cast<__half2*>(&h));
    ax = fmaf(w, v.x, ax);
    ay = fmaf(w, v.y, ay);
}

// Aggregate one row's chunk (2 feats per lane at byte offset boff within row).
__device__ __forceinline__ void agg_row(const char* Hbase, const int2* __restrict__ pe,
                                        int p, int pend, float& ax, float& ay) {
    for (; p + 4 <= pend; p += 4) {
        int2 e0 = __ldg(pe + p + 0), e1 = __ldg(pe + p + 1);
        int2 e2 = __ldg(pe + p + 2), e3 = __ldg(pe + p + 3);
        uint32_t h0 = *reinterpret_cast<const uint32_t*>(Hbase + (size_t)e0.x * 256);
        uint32_t h1 = *reinterpret_cast<const uint32_t*>(Hbase + (size_t)e1.x * 256);
        uint32_t h2 = *reinterpret_cast<const uint32_t*>(Hbase + (size_t)e2.x * 256);
        uint32_t h3 = *reinterpret_cast<const uint32_t*>(Hbase + (size_t)e3.x * 256);
        agg2(ax, ay, __int_as_float(e0.y), h0);
        agg2(ax, ay, __int_as_float(e1.y), h1);
        agg2(ax, ay, __int_as_float(e2.y), h2);
        agg2(ax, ay, __int_as_float(e3.y), h3);
    }
    for (; p < pend; p++) {
        int2 e = __ldg(pe + p);
        uint32_t h = *reinterpret_cast<const uint32_t*>(Hbase + (size_t)e.x * 256);
        agg2(ax, ay, __int_as_float(e.y), h);
    }
}

// ===========================================================================
// Fused SpMM+GEMM (N=128): Cout = (relu(spmm(Hin)+bias)) @ Wpacked
// CTA = 128 rows; per chunk: warp w aggregates rows w*16..+15 (2 feats/lane)
// straight into bf16 hi/lo A-tiles, then MMA. Hin fp16 [M][128].
// ===========================================================================
__global__ void __launch_bounds__(256, 2) fused_spmm_gemm128(
    const __half* __restrict__ Hin, const int* __restrict__ rp,
    const int2* __restrict__ pe, const float* __restrict__ bias,
    const uint32_t* __restrict__ Wph, const uint32_t* __restrict__ Wpl,
    __half* __restrict__ Cout, int M) {
    extern __shared__ uint32_t sm[];
    uint32_t* AH = sm + AH_OFF;
    uint32_t* AL = sm + AL_OFF;
    uint32_t* BH = sm + BH_OFF;
    uint32_t* BL = sm + BL_OFF;

    const int t = threadIdx.x;
    const int lane = t & 31;
    const int wid = t >> 5;
    const int warpM = wid >> 1;
    const int warpN = wid & 1;
    const int row0 = blockIdx.x * 128;

    float acc[2][8][4];
#pragma unroll
    for (int mt = 0; mt < 2; mt++)
#pragma unroll
        for (int nt = 0; nt < 8; nt++)
#pragma unroll
            for (int e = 0; e < 4; e++) acc[mt][nt][e] = 0.f;

    const int r4 = lane >> 2;
    const int q4 = lane & 3;

#pragma unroll
    for (int c = 0; c < 2; c++) {
        __syncthreads();   // tiles free (prev chunk MMA done)

        // ---- aggregation into A tiles ----
        const char* Hc = reinterpret_cast<const char*>(Hin) + c * 128 + lane * 4;
        float b0 = __ldg(bias + c * 64 + lane * 2);
        float b1 = __ldg(bias + c * 64 + lane * 2 + 1);
        for (int i = 0; i < 16; i++) {
            int mrow = wid * 16 + i;
            int grow = row0 + mrow;
            float ax = 0.f, ay = 0.f;
            if (grow < M) {
                int p = __ldg(rp + grow);
                int pend = __ldg(rp + grow + 1);
                agg_row(Hc, pe, p, pend, ax, ay);
            }
            float v0 = fmaxf(ax + b0, 0.f);
            float v1 = fmaxf(ay + b1, 0.f);
            uint32_t h, lo;
            cvt_hilo(v0, v1, h, lo);
            AH[mrow * 36 + lane] = h;
            AL[mrow * 36 + lane] = lo;
        }
        // ---- W chunk stage ----
#pragma unroll
        for (int l = 0; l < 4; l++) {
            int q = t + l * 256;
            int k2 = q >> 5;
            int n4 = q & 31;
            size_t goff = (size_t)(c * 32 + k2) * 128 + n4 * 4;
            uint4 vh = __ldg(reinterpret_cast<const uint4*>(Wph + goff));
            uint4 vl = __ldg(reinterpret_cast<const uint4*>(Wpl + goff));
            *reinterpret_cast<uint4*>(&BH[k2 * 136 + n4 * 4]) = vh;
            *reinterpret_cast<uint4*>(&BL[k2 * 136 + n4 * 4]) = vl;
        }
        __syncthreads();

        // ---- MMA for this chunk ----
#pragma unroll
        for (int k8 = 0; k8 < 4; k8++) {
            int klo = k8 * 8 + q4;
            uint32_t ah[2][4], al[2][4];
#pragma unroll
            for (int mt = 0; mt < 2; mt++) {
                int base = (warpM * 32 + mt * 16 + r4) * 36;
                ah[mt][0] = AH[base + klo];
                ah[mt][1] = AH[base + 8 * 36 + klo];
                ah[mt][2] = AH[base + klo + 4];
                ah[mt][3] = AH[base + 8 * 36 + klo + 4];
                al[mt][0] = AL[base + klo];
                al[mt][1] = AL[base + 8 * 36 + klo];
                al[mt][2] = AL[base + klo + 4];
                al[mt][3] = AL[base + 8 * 36 + klo + 4];
            }
#pragma unroll
            for (int nt = 0; nt < 8; nt++) {
                int nB = warpN * 64 + nt * 8 + r4;
                uint32_t bh0 = BH[klo * 136 + nB];
                uint32_t bh1 = BH[(klo + 4) * 136 + nB];
                uint32_t bl0 = BL[klo * 136 + nB];
                uint32_t bl1 = BL[(klo + 4) * 136 + nB];
#pragma unroll
                for (int mt = 0; mt < 2; mt++) {
                    mma16816(acc[mt][nt], ah[mt], bh0, bh1);
                    mma16816(acc[mt][nt], ah[mt], bl0, bl1);
                    mma16816(acc[mt][nt], al[mt], bh0, bh1);
                }
            }
        }
    }

#pragma unroll
    for (int mt = 0; mt < 2; mt++) {
        int rowA = row0 + warpM * 32 + mt * 16 + r4;
        int rowB = rowA + 8;
#pragma unroll
        for (int nt = 0; nt < 8; nt++) {
            int col = warpN * 64 + nt * 8 + q4 * 2;
            if (rowA < M)
                *reinterpret_cast<__half2*>(Cout + (size_t)rowA * 128 + col) =
                    __floats2half2_rn(acc[mt][nt][0], acc[mt][nt][1]);
            if (rowB < M)
                *reinterpret_cast<__half2*>(Cout + (size_t)rowB * 128 + col) =
                    __floats2half2_rn(acc[mt][nt][2], acc[mt][nt][3]);
        }
    }
}

// ===========================================================================
// Fused SpMM+GEMM (N=40): Ch = (relu(spmm(Hin)+bias)) @ W2packed
// Warp = 16 rows; 5 n-tiles cover 40 cols. B tile stride 44 (conflict-free).
// ===========================================================================
__global__ void __launch_bounds__(256, 2) fused_spmm_gemm40(
    const __half* __restrict__ Hin, const int* __restrict__ rp,
    const int2* __restrict__ pe, const float* __restrict__ bias,
    const uint32_t* __restrict__ Wph, const uint32_t* __restrict__ Wpl,
    __half* __restrict__ Cout, int M) {
    extern __shared__ uint32_t sm[];
    uint32_t* AH = sm + AH_OFF;
    uint32_t* AL = sm + AL_OFF;
    uint32_t* BH = sm + B40H_OFF;
    uint32_t* BL = sm + B40L_OFF;

    const int t = threadIdx.x;
    const int lane = t & 31;
    const int wid = t >> 5;
    const int row0 = blockIdx.x * 128;

    float acc[5][4];
#pragma unroll
    for (int nt = 0; nt < 5; nt++)
#pragma unroll
        for (int e = 0; e < 4; e++) acc[nt][e] = 0.f;

    const int r4 = lane >> 2;
    const int q4 = lane & 3;

#pragma unroll
    for (int c = 0; c < 2; c++) {
        __syncthreads();

        // ---- aggregation into A tiles ----
        const char* Hc = reinterpret_cast<const char*>(Hin) + c * 128 + lane * 4;
        float b0 = __ldg(bias + c * 64 + lane * 2);
        float b1 = __ldg(bias + c * 64 + lane * 2 + 1);
        for (int i = 0; i < 16; i++) {
            int mrow = wid * 16 + i;
            int grow = row0 + mrow;
            float ax = 0.f, ay = 0.f;
            if (grow < M) {
                int p = __ldg(rp + grow);
                int pend = __ldg(rp + grow + 1);
                agg_row(Hc, pe, p, pend, ax, ay);
            }
            float v0 = fmaxf(ax + b0, 0.f);
            float v1 = fmaxf(ay + b1, 0.f);
            uint32_t h, lo;
            cvt_hilo(v0, v1, h, lo);
            AH[mrow * 36 + lane] = h;
            AL[mrow * 36 + lane] = lo;
        }
        // ---- W2 chunk stage: 32 k2 x 40 n per plane (1280 u32, 5/thread) ----
#pragma unroll
        for (int l = 0; l < 5; l++) {
            int q = t + l * 256;
            int k2 = q / 40;
            int n = q - k2 * 40;
            size_t goff = (size_t)(c * 32 + k2) * 40 + n;
            BH[k2 * 44 + n] = __ldg(Wph + goff);
            BL[k2 * 44 + n] = __ldg(Wpl + goff);
        }
        __syncthreads();

        // ---- MMA: warp covers rows wid*16..+15, all 40 cols ----
#pragma unroll
        for (int k8 = 0; k8 < 4; k8++) {
            int klo = k8 * 8 + q4;
            int base = (wid * 16 + r4) * 36;
            uint32_t ah[4], al[4];
            ah[0] = AH[base + klo];
            ah[1] = AH[base + 8 * 36 + klo];
            ah[2] = AH[base + klo + 4];
            ah[3] = AH[base + 8 * 36 + klo + 4];
            al[0] = AL[base + klo];
            al[1] = AL[base + 8 * 36 + klo];
            al[2] = AL[base + klo + 4];
            al[3] = AL[base + 8 * 36 + klo + 4];
#pragma unroll
            for (int nt = 0; nt < 5; nt++) {
                int nB = nt * 8 + r4;
                uint32_t bh0 = BH[klo * 44 + nB];
                uint32_t bh1 = BH[(klo + 4) * 44 + nB];
                uint32_t bl0 = BL[klo * 44 + nB];
                uint32_t bl1 = BL[(klo + 4) * 44 + nB];
                mma16816(acc[nt], ah, bh0, bh1);
                mma16816(acc[nt], ah, bl0, bl1);
                mma16816(acc[nt], al, bh0, bh1);
            }
        }
    }

    // ---- epilogue: fp16 logits ----
    int rowA = row0 + wid * 16 + r4;
    int rowB = rowA + 8;
#pragma unroll
    for (int nt = 0; nt < 5; nt++) {
        int col = nt * 8 + q4 * 2;
        if (rowA < M)
            *reinterpret_cast<__half2*>(Cout + (size_t)rowA * 40 + col) =
                __floats2half2_rn(acc[nt][0], acc[nt][1]);
        if (rowB < M)
            *reinterpret_cast<__half2*>(Cout + (size_t)rowB * 40 + col) =
                __floats2half2_rn(acc[nt][2], acc[nt][3]);
    }
}

// ===========================================================================
// CSR build: zero -> histogram -> 2-kernel scan -> scatter
// ===========================================================================
__global__ void zero_int4(int4* p, int n4) {
    int i = blockIdx.x * blockDim.x + threadIdx.x;
    if (i < n4) p[i] = make_int4(0, 0, 0, 0);
}

__global__ void hist_dst4(const int4* __restrict__ dst4, int* __restrict__ cnt, int n4) {
    int e = blockIdx.x * blockDim.x + threadIdx.x;
    if (e >= n4) return;
    int4 d = __ldg(dst4 + e);
    atomicAdd(&cnt[d.x], 1);
    atomicAdd(&cnt[d.y], 1);
    atomicAdd(&cnt[d.z], 1);
    atomicAdd(&cnt[d.w], 1);
}

__global__ void scan_p1(const int* __restrict__ cnt, int* __restrict__ tmp,
                        int* __restrict__ bsum, int n) {
    __shared__ int wsum[8];
    const int lane = threadIdx.x & 31;
    const int wid  = threadIdx.x >> 5;
    int i = blockIdx.x * 256 + threadIdx.x;
    int v = (i < n) ? cnt[i] : 0;
    int incl = v;
#pragma unroll
    for (int o = 1; o < 32; o <<= 1) {
        int tt = __shfl_up_sync(0xffffffffu, incl, o);
        if (lane >= o) incl += tt;
    }
    if (lane == 31) wsum[wid] = incl;
    __syncthreads();
    if (wid == 0) {
        int s = (lane < 8) ? wsum[lane] : 0;
#pragma unroll
        for (int o = 1; o < 8; o <<= 1) {
            int tt = __shfl_up_sync(0xffffffffu, s, o);
            if (lane >= o) s += tt;
        }
        if (lane < 8) wsum[lane] = s;
    }
    __syncthreads();
    int excl = (wid ? wsum[wid - 1] : 0) + incl - v;
    if (i < n) tmp[i] = excl;
    if (threadIdx.x == 255) bsum[blockIdx.x] = excl + v;
}

__global__ void scan_p3(const int* __restrict__ tmp, const int* __restrict__ bsum,
                        int* __restrict__ rp, int* __restrict__ cursor,
                        int n, int nb, int nE) {
    __shared__ int red[8];
    const int lane = threadIdx.x & 31;
    const int wid  = threadIdx.x >> 5;
    int v = (threadIdx.x < nb && threadIdx.x < blockIdx.x) ? __ldg(bsum + threadIdx.x) : 0;
#pragma unroll
    for (int o = 16; o > 0; o >>= 1) v += __shfl_xor_sync(0xffffffffu, v, o);
    if (lane == 0) red[wid] = v;
    __syncthreads();
    if (threadIdx.x == 0) {
        int s = 0;
#pragma unroll
        for (int j = 0; j < 8; j++) s += red[j];
        red[0] = s;
    }
    __syncthreads();
    int off = red[0];
    int i = blockIdx.x * 256 + threadIdx.x;
    if (i < n) {
        int val = tmp[i] + off;
        rp[i] = val;
        cursor[i] = val;
    }
    if (blockIdx.x == 0 && threadIdx.x == 0) rp[n] = nE;
}

__global__ void scatter_edges4(const int* __restrict__ src, const int* __restrict__ dst,
                               const float* __restrict__ w, int* __restrict__ cursor,
                               int2* __restrict__ pe, int nE) {
    int i = blockIdx.x * blockDim.x + threadIdx.x;
    int e0 = i * 4;
    if (e0 + 4 <= nE) {
        int4 s = __ldg((const int4*)(src + e0));
        int4 d = __ldg((const int4*)(dst + e0));
        float4 ww = __ldg((const float4*)(w + e0));
        int p0 = atomicAdd(&cursor[d.x], 1);
        pe[p0] = make_int2(s.x, __float_as_int(ww.x));
        int p1 = atomicAdd(&cursor[d.y], 1);
        pe[p1] = make_int2(s.y, __float_as_int(ww.y));
        int p2 = atomicAdd(&cursor[d.z], 1);
        pe[p2] = make_int2(s.z, __float_as_int(ww.z));
        int p3 = atomicAdd(&cursor[d.w], 1);
        pe[p3] = make_int2(s.w, __float_as_int(ww.w));
    } else {
        for (int e = e0; e < nE; e++) {
            int dd = __ldg(dst + e);
            int pos = atomicAdd(&cursor[dd], 1);
            pe[pos] = make_int2(__ldg(src + e), __float_as_int(__ldg(w + e)));
        }
    }
}

// ===========================================================================
// Gather SpMM (feat=40, fp16 logits, fp32 accum) + bias + log_softmax
// ===========================================================================
__global__ void __launch_bounds__(256) spmm_csr40_lsm(
    const __half* __restrict__ C, const int* __restrict__ rp,
    const int2* __restrict__ pe, const float* __restrict__ b,
    float* __restrict__ out, int M) {
    int row = blockIdx.x * 8 + (threadIdx.x >> 5);
    int lane = threadIdx.x & 31;
    if (row >= M) return;
    int p  = __ldg(rp + row);
    int pend = __ldg(rp + row + 1);

    float a0 = 0.f, a1 = 0.f;
    for (; p + 2 <= pend; p += 2) {
        int2 e0 = __ldg(pe + p), e1 = __ldg(pe + p + 1);
        float w0 = __int_as_float(e0.y), w1 = __int_as_float(e1.y);
        const __half* c0 = C + (size_t)e0.x * 40;
        const __half* c1 = C + (size_t)e1.x * 40;
        float x0 = __half2float(__ldg(c0 + lane));
        float x1 = __half2float(__ldg(c1 + lane));
        float y0 = (lane < 8) ? __half2float(__ldg(c0 + 32 + lane)) : 0.f;
        float y1 = (lane < 8) ? __half2float(__ldg(c1 + 32 + lane)) : 0.f;
        a0 = fmaf(w0, x0, a0); a0 = fmaf(w1, x1, a0);
        a1 = fmaf(w0, y0, a1); a1 = fmaf(w1, y1, a1);
    }
    if (p < pend) {
        int2 e = __ldg(pe + p);
        float w = __int_as_float(e.y);
        const __half* c0 = C + (size_t)e.x * 40;
        a0 = fmaf(w, __half2float(__ldg(c0 + lane)), a0);
        if (lane < 8) a1 = fmaf(w, __half2float(__ldg(c0 + 32 + lane)), a1);
    }

    float v0 = a0 + __ldg(b + lane);
    float v1 = (lane < 8) ? (a1 + __ldg(b + 32 + lane)) : -INFINITY;

    float m = fmaxf(v0, v1);
#pragma unroll
    for (int o = 16; o > 0; o >>= 1) m = fmaxf(m, __shfl_xor_sync(0xffffffffu, m, o));
    float s = __expf(v0 - m) + ((lane < 8) ? __expf(v1 - m) : 0.f);
#pragma unroll
    for (int o = 16; o > 0; o >>= 1) s += __shfl_xor_sync(0xffffffffu, s, o);
    float ls = m + __logf(s);

    out[(size_t)row * 40 + lane] = v0 - ls;
    if (lane < 8) out[(size_t)row * 40 + 32 + lane] = v1 - ls;
}

// ===========================================================================
extern "C" void kernel_launch(void* const* d_in, const int* in_sizes, int n_in,
                              void* d_out, int out_size) {
    const float* x    = (const float*)d_in[0];
    const int*   esrc = (const int*)  d_in[1];
    const int*   edst = (const int*)  d_in[2];
    const float* ew   = (const float*)d_in[3];
    const float* W1   = (const float*)d_in[4];
    const float* b1   = (const float*)d_in[5];
    const float* Wh   = (const float*)d_in[6];
    const float* bh   = (const float*)d_in[7];
    const float* W2   = (const float*)d_in[8];
    const float* b2   = (const float*)d_in[9];
    float* out = (float*)d_out;

    const int M  = in_sizes[0] / NFEAT;   // 50000
    const int nE = in_sizes[1];           // 1600000

    __half *Ah, *Bh, *Ch;
    int *cnt, *cursor, *rp, *tmp, *bsum;
    int2 *pe;
    uint32_t *W1h, *W1l, *Whh, *Whl, *W2h, *W2l;
    cudaGetSymbolAddress((void**)&Ah, g_Ah);
    cudaGetSymbolAddress((void**)&Bh, g_Bh);
    cudaGetSymbolAddress((void**)&Ch, g_Ch);
    cudaGetSymbolAddress((void**)&cnt, g_cnt);
    cudaGetSymbolAddress((void**)&cursor, g_cursor);
    cudaGetSymbolAddress((void**)&rp, g_rp);
    cudaGetSymbolAddress((void**)&tmp, g_tmp);
    cudaGetSymbolAddress((void**)&bsum, g_bsum);
    cudaGetSymbolAddress((void**)&pe, g_pe);
    cudaGetSymbolAddress((void**)&W1h, g_W1h);
    cudaGetSymbolAddress((void**)&W1l, g_W1l);
    cudaGetSymbolAddress((void**)&Whh, g_Whh);
    cudaGetSymbolAddress((void**)&Whl, g_Whl);
    cudaGetSymbolAddress((void**)&W2h, g_W2h);
    cudaGetSymbolAddress((void**)&W2l, g_W2l);

    static cudaStream_t s2 = nullptr;
    static cudaEvent_t evF = nullptr, evJ = nullptr;
    if (!s2) {
        cudaStreamCreateWithFlags(&s2, cudaStreamNonBlocking);
        cudaEventCreateWithFlags(&evF, cudaEventDisableTiming);
        cudaEventCreateWithFlags(&evJ, cudaEventDisableTiming);
        cudaFuncSetAttribute(mma_gemm128,
                             cudaFuncAttributeMaxDynamicSharedMemorySize, SM_U32 * 4);
        cudaFuncSetAttribute(fused_spmm_gemm128,
                             cudaFuncAttributeMaxDynamicSharedMemorySize, SM_U32 * 4);
        cudaFuncSetAttribute(fused_spmm_gemm40,
                             cudaFuncAttributeMaxDynamicSharedMemorySize, SM40_U32 * 4);
    }

    const int nb = (M + 255) / 256;           // 196
    const int gemmBlocks = (M + 127) / 128;   // 391
    const int spmmBlocks = (M + 7) / 8;
    const int nE4 = (nE + 3) / 4;

    // ---- Fork: CSR build on s2, weight pack + layer-1 GEMM on main ----
    cudaEventRecord(evF, 0);
    cudaStreamWaitEvent(s2, evF, 0);

    zero_int4<<<(M / 4 + 255) / 256, 256, 0, s2>>>((int4*)cnt, (M + 3) / 4);
    hist_dst4<<<((nE / 4) + 255) / 256, 256, 0, s2>>>((const int4*)edst, cnt, nE / 4);
    scan_p1<<<nb, 256, 0, s2>>>(cnt, tmp, bsum, M);
    scan_p3<<<nb, 256, 0, s2>>>(tmp, bsum, rp, cursor, M, nb, nE);
    scatter_edges4<<<(nE4 + 255) / 256, 256, 0, s2>>>(esrc, edst, ew, cursor, pe, nE);
    cudaEventRecord(evJ, s2);

    conv_weights<<<170, 256>>>(W1, Wh, W2, W1h, W1l, Whh, Whl, W2h, W2l);
    mma_gemm128<<<gemmBlocks, 256, SM_U32 * 4>>>(x, W1h, W1l, Ah, M, NFEAT);

    cudaStreamWaitEvent(0, evJ, 0);   // join

    // Layer 2: aggregate(Ah)+b1+relu -> GEMM(Wh) -> Bh
    fused_spmm_gemm128<<<gemmBlocks, 256, SM_U32 * 4>>>(Ah, rp, pe, b1, Whh, Whl, Bh, M);

    // Layer 3: aggregate(Bh)+bh+relu -> GEMM(W2) -> Ch (fp16 logits)
    fused_spmm_gemm40<<<gemmBlocks, 256, SM40_U32 * 4>>>(Bh, rp, pe, bh, W2h, W2l, Ch, M);

    // Final aggregation + bias + log_softmax
    spmm_csr40_lsm<<<spmmBlocks, 256>>>(Ch, rp, pe, b2, out, M);
}

// round 11
// speedup vs baseline: 1.8378x; 1.8378x over previous
#include <cuda_runtime.h>
#include <cuda_bf16.h>
#include <cuda_fp16.h>
#include <math.h>
#include <cstdint>

// ---------------------------------------------------------------------------
// GCN: 3x { H = A_sparse @ (H @ W) + b (,ReLU) } -> log_softmax
// N=50000, E=1.6M, 512 -> 128 -> 128 -> 40
// Round 11: revert to R9 structure; fuse GEMM3 into spmm2 epilogue (row-local,
//           preserves gather shape); self-zeroing histogram (drop zero kernel).
// ---------------------------------------------------------------------------

#define NNODES 50000
#define NEDGES 1600000
#define NFEAT 512
#define NHID  128
#define NCLASS 40

// Scratch (__device__ globals; no allocations allowed)
__device__ __half g_Ah[NNODES * NHID];   // gemm output buffer
__device__ __half g_Bh[NNODES * NHID];   // spmm1 output buffer
__device__ __half g_Ch[NNODES * NCLASS]; // fused spmm2+gemm40 output (logits)
__device__ int    g_cnt[NNODES];         // histogram (self-restoring to zero)
__device__ int    g_cursor[NNODES];
__device__ int    g_rp[NNODES + 1];
__device__ int    g_tmp[NNODES];
__device__ int    g_bsum[256];
__device__ int2   g_pe[NEDGES];          // packed (src, weight-bits)
// Pre-packed weights: bf16x2 k-pairs, layout [k2][n] (n=128)
__device__ uint32_t g_W1h[256 * 128];
__device__ uint32_t g_W1l[256 * 128];
__device__ uint32_t g_Whh[64 * 128];
__device__ uint32_t g_Whl[64 * 128];

// ===========================================================================
// helpers
// ===========================================================================
__device__ __forceinline__ void cvt_hilo(float x, float y, uint32_t& hi, uint32_t& lo) {
    __nv_bfloat16 hx = __float2bfloat16(x);
    __nv_bfloat16 hy = __float2bfloat16(y);
    float rx = x - __bfloat162float(hx);
    float ry = y - __bfloat162float(hy);
    __nv_bfloat162 H; H.x = hx; H.y = hy;
    __nv_bfloat162 L; L.x = __float2bfloat16(rx); L.y = __float2bfloat16(ry);
    hi = *reinterpret_cast<uint32_t*>(&H);
    lo = *reinterpret_cast<uint32_t*>(&L);
}

__device__ __forceinline__ void mma16816(float* d, const uint32_t* a, uint32_t b0, uint32_t b1) {
    asm volatile(
        "mma.sync.aligned.m16n8k16.row.col.f32.bf16.bf16.f32 "
        "{%0,%1,%2,%3}, {%4,%5,%6,%7}, {%8,%9}, {%0,%1,%2,%3};"
        : "+f"(d[0]), "+f"(d[1]), "+f"(d[2]), "+f"(d[3])
        : "r"(a[0]), "r"(a[1]), "r"(a[2]), "r"(a[3]), "r"(b0), "r"(b1));
}

__device__ __forceinline__ float4 load4f(const float* p) {
    return *reinterpret_cast<const float4*>(p);
}
__device__ __forceinline__ float4 load4f(const __half* p) {
    uint2 u = *reinterpret_cast<const uint2*>(p);
    float2 a = __half22float2(*reinterpret_cast<__half2*>(&u.x));
    float2 b = __half22float2(*reinterpret_cast<__half2*>(&u.y));
    return make_float4(a.x, a.y, b.x, b.y);
}

// SMEM layout (u32 units). A tiles: [m=128][k2=32 + pad4]. B: [k2=32][n=128+8].
#define AH_OFF 0
#define AL_OFF 4608
#define BH_OFF 9216
#define BL_OFF 13568
#define SM_U32 17920   // 71680 bytes

// ===========================================================================
// Weight pre-pack: W[K][128] fp32 -> hi/lo bf16x2 planes [K/2][128]
// ===========================================================================
__global__ void conv_weights(const float* __restrict__ W1, const float* __restrict__ Wh,
                             uint32_t* __restrict__ W1h, uint32_t* __restrict__ W1l,
                             uint32_t* __restrict__ Whh, uint32_t* __restrict__ Whl) {
    int i = blockIdx.x * 256 + threadIdx.x;
    if (i < 256 * 128) {
        int k2 = i >> 7, n = i & 127;
        float v0 = __ldg(W1 + (size_t)(2 * k2) * 128 + n);
        float v1 = __ldg(W1 + (size_t)(2 * k2 + 1) * 128 + n);
        uint32_t h, lo;
        cvt_hilo(v0, v1, h, lo);
        W1h[i] = h; W1l[i] = lo;
    } else if (i < 256 * 128 + 64 * 128) {
        int j = i - 256 * 128;
        int k2 = j >> 7, n = j & 127;
        float v0 = __ldg(Wh + (size_t)(2 * k2) * 128 + n);
        float v1 = __ldg(Wh + (size_t)(2 * k2 + 1) * 128 + n);
        uint32_t h, lo;
        cvt_hilo(v0, v1, h, lo);
        Whh[j] = h; Whl[j] = lo;
    }
}

// ===========================================================================
// mma.sync GEMM: C[M,128] = A[M,K] @ W[K,128]; A fp32/fp16; W pre-packed.
// bf16 hi/lo split, fp32 accumulate, fp16 out. CTA 128x128, 8 warps.
// ===========================================================================
template <typename TIn>
__global__ void __launch_bounds__(256, 2) mma_gemm128(
    const TIn* __restrict__ A,
    const uint32_t* __restrict__ Wph, const uint32_t* __restrict__ Wpl,
    __half* __restrict__ C, int M, int K) {
    extern __shared__ uint32_t sm[];
    uint32_t* AH = sm + AH_OFF;
    uint32_t* AL = sm + AL_OFF;
    uint32_t* BH = sm + BH_OFF;
    uint32_t* BL = sm + BL_OFF;

    const int t = threadIdx.x;
    const int lane = t & 31;
    const int wid = t >> 5;
    const int warpM = wid >> 1;
    const int warpN = wid & 1;
    const int row0 = blockIdx.x * 128;

    float acc[2][8][4];
#pragma unroll
    for (int mt = 0; mt < 2; mt++)
#pragma unroll
        for (int nt = 0; nt < 8; nt++)
#pragma unroll
            for (int e = 0; e < 4; e++) acc[mt][nt][e] = 0.f;

    const int r4 = lane >> 2;
    const int q4 = lane & 3;

    const int nChunks = K >> 6;
    for (int c = 0; c < nChunks; c++) {
        const int k0 = c << 6;
        const int k0h = c << 5;
        __syncthreads();

#pragma unroll
        for (int l = 0; l < 8; l++) {
            int q = t + l * 256;
            int m = q >> 4;
            int c4 = q & 15;
            float4 v = make_float4(0.f, 0.f, 0.f, 0.f);
            if (row0 + m < M)
                v = load4f(A + (size_t)(row0 + m) * K + k0 + c4 * 4);
            uint32_t h0, l0, h1, l1;
            cvt_hilo(v.x, v.y, h0, l0);
            cvt_hilo(v.z, v.w, h1, l1);
            int base = m * 36 + c4 * 2;
            AH[base] = h0; AH[base + 1] = h1;
            AL[base] = l0; AL[base + 1] = l1;
        }
#pragma unroll
        for (int l = 0; l < 4; l++) {
            int q = t + l * 256;
            int k2 = q >> 5;
            int n4 = q & 31;
            size_t goff = (size_t)(k0h + k2) * 128 + n4 * 4;
            uint4 vh = __ldg(reinterpret_cast<const uint4*>(Wph + goff));
            uint4 vl = __ldg(reinterpret_cast<const uint4*>(Wpl + goff));
            *reinterpret_cast<uint4*>(&BH[k2 * 136 + n4 * 4]) = vh;
            *reinterpret_cast<uint4*>(&BL[k2 * 136 + n4 * 4]) = vl;
        }
        __syncthreads();

#pragma unroll
        for (int k8 = 0; k8 < 4; k8++) {
            int klo = k8 * 8 + q4;
            uint32_t ah[2][4], al[2][4];
#pragma unroll
            for (int mt = 0; mt < 2; mt++) {
                int base = (warpM * 32 + mt * 16 + r4) * 36;
                ah[mt][0] = AH[base + klo];
                ah[mt][1] = AH[base + 8 * 36 + klo];
                ah[mt][2] = AH[base + klo + 4];
                ah[mt][3] = AH[base + 8 * 36 + klo + 4];
                al[mt][0] = AL[base + klo];
                al[mt][1] = AL[base + 8 * 36 + klo];
                al[mt][2] = AL[base + klo + 4];
                al[mt][3] = AL[base + 8 * 36 + klo + 4];
            }
#pragma unroll
            for (int nt = 0; nt < 8; nt++) {
                int nB = warpN * 64 + nt * 8 + r4;
                uint32_t bh0 = BH[klo * 136 + nB];
                uint32_t bh1 = BH[(klo + 4) * 136 + nB];
                uint32_t bl0 = BL[klo * 136 + nB];
                uint32_t bl1 = BL[(klo + 4) * 136 + nB];
#pragma unroll
                for (int mt = 0; mt < 2; mt++) {
                    mma16816(acc[mt][nt], ah[mt], bh0, bh1);
                    mma16816(acc[mt][nt], ah[mt], bl0, bl1);
                    mma16816(acc[mt][nt], al[mt], bh0, bh1);
                }
            }
        }
    }

#pragma unroll
    for (int mt = 0; mt < 2; mt++) {
        int rowA = row0 + warpM * 32 + mt * 16 + r4;
        int rowB = rowA + 8;
#pragma unroll
        for (int nt = 0; nt < 8; nt++) {
            int col = warpN * 64 + nt * 8 + q4 * 2;
            if (rowA < M)
                *reinterpret_cast<__half2*>(C + (size_t)rowA * 128 + col) =
                    __floats2half2_rn(acc[mt][nt][0], acc[mt][nt][1]);
            if (rowB < M)
                *reinterpret_cast<__half2*>(C + (size_t)rowB * 128 + col) =
                    __floats2half2_rn(acc[mt][nt][2], acc[mt][nt][3]);
        }
    }
}

// ===========================================================================
// CSR build: histogram (self-zeroing scan) -> 2-kernel scan -> scatter
// ===========================================================================
__global__ void hist_dst4(const int4* __restrict__ dst4, int* __restrict__ cnt, int n4) {
    int e = blockIdx.x * blockDim.x + threadIdx.x;
    if (e >= n4) return;
    int4 d = __ldg(dst4 + e);
    atomicAdd(&cnt[d.x], 1);
    atomicAdd(&cnt[d.y], 1);
    atomicAdd(&cnt[d.z], 1);
    atomicAdd(&cnt[d.w], 1);
}

// Reads cnt, zeroes it (restores invariant cnt==0 for the next replay).
__global__ void scan_p1(int* __restrict__ cnt, int* __restrict__ tmp,
                        int* __restrict__ bsum, int n) {
    __shared__ int wsum[8];
    const int lane = threadIdx.x & 31;
    const int wid  = threadIdx.x >> 5;
    int i = blockIdx.x * 256 + threadIdx.x;
    int v = 0;
    if (i < n) { v = cnt[i]; cnt[i] = 0; }
    int incl = v;
#pragma unroll
    for (int o = 1; o < 32; o <<= 1) {
        int tt = __shfl_up_sync(0xffffffffu, incl, o);
        if (lane >= o) incl += tt;
    }
    if (lane == 31) wsum[wid] = incl;
    __syncthreads();
    if (wid == 0) {
        int s = (lane < 8) ? wsum[lane] : 0;
#pragma unroll
        for (int o = 1; o < 8; o <<= 1) {
            int tt = __shfl_up_sync(0xffffffffu, s, o);
            if (lane >= o) s += tt;
        }
        if (lane < 8) wsum[lane] = s;
    }
    __syncthreads();
    int excl = (wid ? wsum[wid - 1] : 0) + incl - v;
    if (i < n) tmp[i] = excl;
    if (threadIdx.x == 255) bsum[blockIdx.x] = excl + v;
}

__global__ void scan_p3(const int* __restrict__ tmp, const int* __restrict__ bsum,
                        int* __restrict__ rp, int* __restrict__ cursor,
                        int n, int nb, int nE) {
    __shared__ int red[8];
    const int lane = threadIdx.x & 31;
    const int wid  = threadIdx.x >> 5;
    int v = (threadIdx.x < nb && threadIdx.x < blockIdx.x) ? __ldg(bsum + threadIdx.x) : 0;
#pragma unroll
    for (int o = 16; o > 0; o >>= 1) v += __shfl_xor_sync(0xffffffffu, v, o);
    if (lane == 0) red[wid] = v;
    __syncthreads();
    if (threadIdx.x == 0) {
        int s = 0;
#pragma unroll
        for (int j = 0; j < 8; j++) s += red[j];
        red[0] = s;
    }
    __syncthreads();
    int off = red[0];
    int i = blockIdx.x * 256 + threadIdx.x;
    if (i < n) {
        int val = tmp[i] + off;
        rp[i] = val;
        cursor[i] = val;
    }
    if (blockIdx.x == 0 && threadIdx.x == 0) rp[n] = nE;
}

__global__ void scatter_edges4(const int* __restrict__ src, const int* __restrict__ dst,
                               const float* __restrict__ w, int* __restrict__ cursor,
                               int2* __restrict__ pe, int nE) {
    int i = blockIdx.x * blockDim.x + threadIdx.x;
    int e0 = i * 4;
    if (e0 + 4 <= nE) {
        int4 s = __ldg((const int4*)(src + e0));
        int4 d = __ldg((const int4*)(dst + e0));
        float4 ww = __ldg((const float4*)(w + e0));
        int p0 = atomicAdd(&cursor[d.x], 1);
        pe[p0] = make_int2(s.x, __float_as_int(ww.x));
        int p1 = atomicAdd(&cursor[d.y], 1);
        pe[p1] = make_int2(s.y, __float_as_int(ww.y));
        int p2 = atomicAdd(&cursor[d.z], 1);
        pe[p2] = make_int2(s.z, __float_as_int(ww.z));
        int p3 = atomicAdd(&cursor[d.w], 1);
        pe[p3] = make_int2(s.w, __float_as_int(ww.w));
    } else {
        for (int e = e0; e < nE; e++) {
            int dd = __ldg(dst + e);
            int pos = atomicAdd(&cursor[dd], 1);
            pe[pos] = make_int2(__ldg(src + e), __float_as_int(__ldg(w + e)));
        }
    }
}

// ===========================================================================
// Gather SpMM (feat=128, fp16 in, fp32 accum, fp16 out) + bias + ReLU
// ===========================================================================
__device__ __forceinline__ void acc4h(float& ax, float& ay, float& az, float& aw,
                                      float w, uint2 r) {
    float2 a01 = __half22float2(*reinterpret_cast<__half2*>(&r.x));
    float2 a23 = __half22float2(*reinterpret_cast<__half2*>(&r.y));
    ax = fmaf(w, a01.x, ax); ay = fmaf(w, a01.y, ay);
    az = fmaf(w, a23.x, az); aw = fmaf(w, a23.y, aw);
}

__device__ __forceinline__ void agg_row128(const char* Hb, const int2* __restrict__ pe,
                                           int p, int pend,
                                           float& ax, float& ay, float& az, float& aw) {
    for (; p + 4 <= pend; p += 4) {
        int2 e0 = __ldg(pe + p + 0), e1 = __ldg(pe + p + 1);
        int2 e2 = __ldg(pe + p + 2), e3 = __ldg(pe + p + 3);
        uint2 r0 = *reinterpret_cast<const uint2*>(Hb + (size_t)e0.x * 256);
        uint2 r1 = *reinterpret_cast<const uint2*>(Hb + (size_t)e1.x * 256);
        uint2 r2 = *reinterpret_cast<const uint2*>(Hb + (size_t)e2.x * 256);
        uint2 r3 = *reinterpret_cast<const uint2*>(Hb + (size_t)e3.x * 256);
        acc4h(ax, ay, az, aw, __int_as_float(e0.y), r0);
        acc4h(ax, ay, az, aw, __int_as_float(e1.y), r1);
        acc4h(ax, ay, az, aw, __int_as_float(e2.y), r2);
        acc4h(ax, ay, az, aw, __int_as_float(e3.y), r3);
    }
    for (; p < pend; p++) {
        int2 e = __ldg(pe + p);
        uint2 r0 = *reinterpret_cast<const uint2*>(Hb + (size_t)e.x * 256);
        acc4h(ax, ay, az, aw, __int_as_float(e.y), r0);
    }
}

__global__ void __launch_bounds__(256) spmm_csr128h(
    const __half* __restrict__ H, const int* __restrict__ rp,
    const int2* __restrict__ pe, const float* __restrict__ bias,
    __half* __restrict__ out, int M) {
    int row = blockIdx.x * 8 + (threadIdx.x >> 5);
    int lane = threadIdx.x & 31;
    if (row >= M) return;
    int p  = __ldg(rp + row);
    int pend = __ldg(rp + row + 1);

    const char* Hb = reinterpret_cast<const char*>(H) + lane * 8;
    float ax = 0.f, ay = 0.f, az = 0.f, aw = 0.f;
    agg_row128(Hb, pe, p, pend, ax, ay, az, aw);

    float4 b4 = *reinterpret_cast<const float4*>(bias + lane * 4);
    __half2 o01 = __floats2half2_rn(fmaxf(ax + b4.x, 0.f), fmaxf(ay + b4.y, 0.f));
    __half2 o23 = __floats2half2_rn(fmaxf(az + b4.z, 0.f), fmaxf(aw + b4.w, 0.f));
    uint2 st;
    st.x = *reinterpret_cast<uint32_t*>(&o01);
    st.y = *reinterpret_cast<uint32_t*>(&o23);
    *reinterpret_cast<uint2*>(reinterpret_cast<char*>(out) + (size_t)row * 256 + lane * 8) = st;
}

// ===========================================================================
// Fused spmm2 + GEMM3: Ch[row][0..39] = relu(spmm(H)[row]+bh) @ W2
// Aggregation identical to spmm_csr128h (1 warp/row); epilogue stages the
// 128-feature row to smem and multiplies by W2 (fp32 smem, conflict-free).
// ===========================================================================
__global__ void __launch_bounds__(256) spmm_gemm40(
    const __half* __restrict__ H, const int* __restrict__ rp,
    const int2* __restrict__ pe, const float* __restrict__ bias,
    const float* __restrict__ W2, __half* __restrict__ Cout, int M) {
    __shared__ float Ws[128][40];    // 20480 B
    __shared__ float rows[8][132];   // 4224 B (pad 132: float4 stores clean)

    const int t = threadIdx.x;
    const int lane = t & 31;
    const int wid = t >> 5;
    int row = blockIdx.x * 8 + wid;

    // Cooperative W2 load (5120 floats, 20/thread)
#pragma unroll
    for (int l = 0; l < 20; l++) {
        int q = t + l * 256;
        Ws[q / 40][q % 40] = __ldg(W2 + q);
    }
    __syncthreads();

    if (row >= M) return;

    int p  = __ldg(rp + row);
    int pend = __ldg(rp + row + 1);
    const char* Hb = reinterpret_cast<const char*>(H) + lane * 8;
    float ax = 0.f, ay = 0.f, az = 0.f, aw = 0.f;
    agg_row128(Hb, pe, p, pend, ax, ay, az, aw);

    float4 b4 = *reinterpret_cast<const float4*>(bias + lane * 4);
    float4 r4v;
    r4v.x = fmaxf(ax + b4.x, 0.f);
    r4v.y = fmaxf(ay + b4.y, 0.f);
    r4v.z = fmaxf(az + b4.z, 0.f);
    r4v.w = fmaxf(aw + b4.w, 0.f);
    *reinterpret_cast<float4*>(&rows[wid][lane * 4]) = r4v;
    __syncwarp();

    // row @ W2: lane handles col=lane (+ col=32+lane for lanes 0..7)
    float a0 = 0.f, a1 = 0.f;
#pragma unroll 8
    for (int k = 0; k < 128; k++) {
        float h = rows[wid][k];                       // broadcast
        a0 = fmaf(h, Ws[k][lane], a0);
        if (lane < 8) a1 = fmaf(h, Ws[k][32 + lane], a1);
    }
    Cout[(size_t)row * 40 + lane] = __float2half_rn(a0);
    if (lane < 8) Cout[(size_t)row * 40 + 32 + lane] = __float2half_rn(a1);
}

// ===========================================================================
// Gather SpMM (feat=40, fp16 logits, fp32 accum) + bias + log_softmax
// ===========================================================================
__global__ void __launch_bounds__(256) spmm_csr40_lsm(
    const __half* __restrict__ C, const int* __restrict__ rp,
    const int2* __restrict__ pe, const float* __restrict__ b,
    float* __restrict__ out, int M) {
    int row = blockIdx.x * 8 + (threadIdx.x >> 5);
    int lane = threadIdx.x & 31;
    if (row >= M) return;
    int p  = __ldg(rp + row);
    int pend = __ldg(rp + row + 1);

    float a0 = 0.f, a1 = 0.f;
    for (; p + 2 <= pend; p += 2) {
        int2 e0 = __ldg(pe + p), e1 = __ldg(pe + p + 1);
        float w0 = __int_as_float(e0.y), w1 = __int_as_float(e1.y);
        const __half* c0 = C + (size_t)e0.x * 40;
        const __half* c1 = C + (size_t)e1.x * 40;
        float x0 = __half2float(__ldg(c0 + lane));
        float x1 = __half2float(__ldg(c1 + lane));
        float y0 = (lane < 8) ? __half2float(__ldg(c0 + 32 + lane)) : 0.f;
        float y1 = (lane < 8) ? __half2float(__ldg(c1 + 32 + lane)) : 0.f;
        a0 = fmaf(w0, x0, a0); a0 = fmaf(w1, x1, a0);
        a1 = fmaf(w0, y0, a1); a1 = fmaf(w1, y1, a1);
    }
    if (p < pend) {
        int2 e = __ldg(pe + p);
        float w = __int_as_float(e.y);
        const __half* c0 = C + (size_t)e.x * 40;
        a0 = fmaf(w, __half2float(__ldg(c0 + lane)), a0);
        if (lane < 8) a1 = fmaf(w, __half2float(__ldg(c0 + 32 + lane)), a1);
    }

    float v0 = a0 + __ldg(b + lane);
    float v1 = (lane < 8) ? (a1 + __ldg(b + 32 + lane)) : -INFINITY;

    float m = fmaxf(v0, v1);
#pragma unroll
    for (int o = 16; o > 0; o >>= 1) m = fmaxf(m, __shfl_xor_sync(0xffffffffu, m, o));
    float s = __expf(v0 - m) + ((lane < 8) ? __expf(v1 - m) : 0.f);
#pragma unroll
    for (int o = 16; o > 0; o >>= 1) s += __shfl_xor_sync(0xffffffffu, s, o);
    float ls = m + __logf(s);

    out[(size_t)row * 40 + lane] = v0 - ls;
    if (lane < 8) out[(size_t)row * 40 + 32 + lane] = v1 - ls;
}

// ===========================================================================
extern "C" void kernel_launch(void* const* d_in, const int* in_sizes, int n_in,
                              void* d_out, int out_size) {
    const float* x    = (const float*)d_in[0];
    const int*   esrc = (const int*)  d_in[1];
    const int*   edst = (const int*)  d_in[2];
    const float* ew   = (const float*)d_in[3];
    const float* W1   = (const float*)d_in[4];
    const float* b1   = (const float*)d_in[5];
    const float* Wh   = (const float*)d_in[6];
    const float* bh   = (const float*)d_in[7];
    const float* W2   = (const float*)d_in[8];
    const float* b2   = (const float*)d_in[9];
    float* out = (float*)d_out;

    const int M  = in_sizes[0] / NFEAT;   // 50000
    const int nE = in_sizes[1];           // 1600000

    __half *Ah, *Bh, *Ch;
    int *cnt, *cursor, *rp, *tmp, *bsum;
    int2 *pe;
    uint32_t *W1h, *W1l, *Whh, *Whl;
    cudaGetSymbolAddress((void**)&Ah, g_Ah);
    cudaGetSymbolAddress((void**)&Bh, g_Bh);
    cudaGetSymbolAddress((void**)&Ch, g_Ch);
    cudaGetSymbolAddress((void**)&cnt, g_cnt);
    cudaGetSymbolAddress((void**)&cursor, g_cursor);
    cudaGetSymbolAddress((void**)&rp, g_rp);
    cudaGetSymbolAddress((void**)&tmp, g_tmp);
    cudaGetSymbolAddress((void**)&bsum, g_bsum);
    cudaGetSymbolAddress((void**)&pe, g_pe);
    cudaGetSymbolAddress((void**)&W1h, g_W1h);
    cudaGetSymbolAddress((void**)&W1l, g_W1l);
    cudaGetSymbolAddress((void**)&Whh, g_Whh);
    cudaGetSymbolAddress((void**)&Whl, g_Whl);

    static cudaStream_t s2 = nullptr;
    static cudaEvent_t evF = nullptr, evJ = nullptr;
    if (!s2) {
        cudaStreamCreateWithFlags(&s2, cudaStreamNonBlocking);
        cudaEventCreateWithFlags(&evF, cudaEventDisableTiming);
        cudaEventCreateWithFlags(&evJ, cudaEventDisableTiming);
        cudaFuncSetAttribute(mma_gemm128<float>,
                             cudaFuncAttributeMaxDynamicSharedMemorySize, SM_U32 * 4);
        cudaFuncSetAttribute(mma_gemm128<__half>,
                             cudaFuncAttributeMaxDynamicSharedMemorySize, SM_U32 * 4);
    }

    const int nb = (M + 255) / 256;           // 196
    const int gemmBlocks = (M + 127) / 128;   // 391
    const int spmmBlocks = (M + 7) / 8;
    const int nE4 = (nE + 3) / 4;

    // ---- Fork: CSR build on s2 (cnt is zero by invariant), main: weights+GEMM1
    cudaEventRecord(evF, 0);
    cudaStreamWaitEvent(s2, evF, 0);

    hist_dst4<<<((nE / 4) + 255) / 256, 256, 0, s2>>>((const int4*)edst, cnt, nE / 4);
    scan_p1<<<nb, 256, 0, s2>>>(cnt, tmp, bsum, M);
    scan_p3<<<nb, 256, 0, s2>>>(tmp, bsum, rp, cursor, M, nb, nE);
    scatter_edges4<<<(nE4 + 255) / 256, 256, 0, s2>>>(esrc, edst, ew, cursor, pe, nE);
    cudaEventRecord(evJ, s2);

    conv_weights<<<160, 256>>>(W1, Wh, W1h, W1l, Whh, Whl);
    mma_gemm128<float><<<gemmBlocks, 256, SM_U32 * 4>>>(x, W1h, W1l, Ah, M, NFEAT);

    cudaStreamWaitEvent(0, evJ, 0);   // join

    // Layer 1 aggregation (fp16 out)
    spmm_csr128h<<<spmmBlocks, 256>>>(Ah, rp, pe, b1, Bh, M);

    // Layer 2 GEMM (fp16 in)
    mma_gemm128<__half><<<gemmBlocks, 256, SM_U32 * 4>>>(Bh, Whh, Whl, Ah, M, NHID);

    // Layer 2 aggregation fused with layer 3 GEMM -> fp16 logits
    spmm_gemm40<<<spmmBlocks, 256>>>(Ah, rp, pe, bh, W2, Ch, M);

    // Final aggregation + bias + log_softmax
    spmm_csr40_lsm<<<spmmBlocks, 256>>>(Ch, rp, pe, b2, out, M);
}

// round 12
// speedup vs baseline: 1.9256x; 1.0478x over previous
#include <cuda_runtime.h>
#include <cuda_bf16.h>
#include <cuda_fp16.h>
#include <math.h>
#include <cstdint>

// ---------------------------------------------------------------------------
// GCN: 3x { H = A_sparse @ (H @ W) + b (,ReLU) } -> log_softmax
// N=50000, E=1.6M, 512 -> 128 -> 128 -> 40
// Round 12: R9 structure (best: 275.7) + self-zeroing scan (no zero kernel)
//           + 8-edge/thread scatter (latency-bound; double outstanding atomics)
// ---------------------------------------------------------------------------

#define NNODES 50000
#define NEDGES 1600000
#define NFEAT 512
#define NHID  128
#define NCLASS 40

// Scratch (__device__ globals; no allocations allowed)
__device__ __half g_Ah[NNODES * NHID];   // GEMM output / spmm input
__device__ __half g_Bh[NNODES * NHID];   // spmm output / GEMM input
__device__ __half g_Ch[NNODES * NCLASS]; // GEMM3 output (fp16 logits)
__device__ int    g_cnt[NNODES];         // histogram (self-restoring to zero)
__device__ int    g_cursor[NNODES];
__device__ int    g_rp[NNODES + 1];
__device__ int    g_tmp[NNODES];
__device__ int    g_bsum[256];
__device__ int2   g_pe[NEDGES];          // packed (src, weight-bits)
// Pre-packed weights: bf16x2 k-pairs, layout [k2][n] (n=128)
__device__ uint32_t g_W1h[256 * 128];
__device__ uint32_t g_W1l[256 * 128];
__device__ uint32_t g_Whh[64 * 128];
__device__ uint32_t g_Whl[64 * 128];

// ===========================================================================
// helpers
// ===========================================================================
__device__ __forceinline__ void cvt_hilo(float x, float y, uint32_t& hi, uint32_t& lo) {
    __nv_bfloat16 hx = __float2bfloat16(x);
    __nv_bfloat16 hy = __float2bfloat16(y);
    float rx = x - __bfloat162float(hx);
    float ry = y - __bfloat162float(hy);
    __nv_bfloat162 H; H.x = hx; H.y = hy;
    __nv_bfloat162 L; L.x = __float2bfloat16(rx); L.y = __float2bfloat16(ry);
    hi = *reinterpret_cast<uint32_t*>(&H);
    lo = *reinterpret_cast<uint32_t*>(&L);
}

__device__ __forceinline__ void mma16816(float* d, const uint32_t* a, uint32_t b0, uint32_t b1) {
    asm volatile(
        "mma.sync.aligned.m16n8k16.row.col.f32.bf16.bf16.f32 "
        "{%0,%1,%2,%3}, {%4,%5,%6,%7}, {%8,%9}, {%0,%1,%2,%3};"
        : "+f"(d[0]), "+f"(d[1]), "+f"(d[2]), "+f"(d[3])
        : "r"(a[0]), "r"(a[1]), "r"(a[2]), "r"(a[3]), "r"(b0), "r"(b1));
}

__device__ __forceinline__ float4 load4f(const float* p) {
    return *reinterpret_cast<const float4*>(p);
}
__device__ __forceinline__ float4 load4f(const __half* p) {
    uint2 u = *reinterpret_cast<const uint2*>(p);
    float2 a = __half22float2(*reinterpret_cast<__half2*>(&u.x));
    float2 b = __half22float2(*reinterpret_cast<__half2*>(&u.y));
    return make_float4(a.x, a.y, b.x, b.y);
}

// SMEM layout (u32 units). A tiles: [m=128][k2=32 + pad4]. B: [k2=32][n=128+8].
#define AH_OFF 0
#define AL_OFF 4608
#define BH_OFF 9216
#define BL_OFF 13568
#define SM_U32 17920   // 71680 bytes

// ===========================================================================
// Weight pre-pack: W[K][128] fp32 -> hi/lo bf16x2 planes [K/2][128]
// ===========================================================================
__global__ void conv_weights(const float* __restrict__ W1, const float* __restrict__ Wh,
                             uint32_t* __restrict__ W1h, uint32_t* __restrict__ W1l,
                             uint32_t* __restrict__ Whh, uint32_t* __restrict__ Whl) {
    int i = blockIdx.x * 256 + threadIdx.x;
    if (i < 256 * 128) {
        int k2 = i >> 7, n = i & 127;
        float v0 = __ldg(W1 + (size_t)(2 * k2) * 128 + n);
        float v1 = __ldg(W1 + (size_t)(2 * k2 + 1) * 128 + n);
        uint32_t h, lo;
        cvt_hilo(v0, v1, h, lo);
        W1h[i] = h; W1l[i] = lo;
    } else if (i < 256 * 128 + 64 * 128) {
        int j = i - 256 * 128;
        int k2 = j >> 7, n = j & 127;
        float v0 = __ldg(Wh + (size_t)(2 * k2) * 128 + n);
        float v1 = __ldg(Wh + (size_t)(2 * k2 + 1) * 128 + n);
        uint32_t h, lo;
        cvt_hilo(v0, v1, h, lo);
        Whh[j] = h; Whl[j] = lo;
    }
}

// ===========================================================================
// mma.sync GEMM: C[M,128] = A[M,K] @ W[K,128]; A fp32/fp16; W pre-packed.
// bf16 hi/lo split, fp32 accumulate, fp16 out. CTA 128x128, 8 warps.
// ===========================================================================
template <typename TIn>
__global__ void __launch_bounds__(256, 2) mma_gemm128(
    const TIn* __restrict__ A,
    const uint32_t* __restrict__ Wph, const uint32_t* __restrict__ Wpl,
    __half* __restrict__ C, int M, int K) {
    extern __shared__ uint32_t sm[];
    uint32_t* AH = sm + AH_OFF;
    uint32_t* AL = sm + AL_OFF;
    uint32_t* BH = sm + BH_OFF;
    uint32_t* BL = sm + BL_OFF;

    const int t = threadIdx.x;
    const int lane = t & 31;
    const int wid = t >> 5;
    const int warpM = wid >> 1;
    const int warpN = wid & 1;
    const int row0 = blockIdx.x * 128;

    float acc[2][8][4];
#pragma unroll
    for (int mt = 0; mt < 2; mt++)
#pragma unroll
        for (int nt = 0; nt < 8; nt++)
#pragma unroll
            for (int e = 0; e < 4; e++) acc[mt][nt][e] = 0.f;

    const int r4 = lane >> 2;
    const int q4 = lane & 3;

    const int nChunks = K >> 6;
    for (int c = 0; c < nChunks; c++) {
        const int k0 = c << 6;
        const int k0h = c << 5;
        __syncthreads();

#pragma unroll
        for (int l = 0; l < 8; l++) {
            int q = t + l * 256;
            int m = q >> 4;
            int c4 = q & 15;
            float4 v = make_float4(0.f, 0.f, 0.f, 0.f);
            if (row0 + m < M)
                v = load4f(A + (size_t)(row0 + m) * K + k0 + c4 * 4);
            uint32_t h0, l0, h1, l1;
            cvt_hilo(v.x, v.y, h0, l0);
            cvt_hilo(v.z, v.w, h1, l1);
            int base = m * 36 + c4 * 2;
            AH[base] = h0; AH[base + 1] = h1;
            AL[base] = l0; AL[base + 1] = l1;
        }
#pragma unroll
        for (int l = 0; l < 4; l++) {
            int q = t + l * 256;
            int k2 = q >> 5;
            int n4 = q & 31;
            size_t goff = (size_t)(k0h + k2) * 128 + n4 * 4;
            uint4 vh = __ldg(reinterpret_cast<const uint4*>(Wph + goff));
            uint4 vl = __ldg(reinterpret_cast<const uint4*>(Wpl + goff));
            *reinterpret_cast<uint4*>(&BH[k2 * 136 + n4 * 4]) = vh;
            *reinterpret_cast<uint4*>(&BL[k2 * 136 + n4 * 4]) = vl;
        }
        __syncthreads();

#pragma unroll
        for (int k8 = 0; k8 < 4; k8++) {
            int klo = k8 * 8 + q4;
            uint32_t ah[2][4], al[2][4];
#pragma unroll
            for (int mt = 0; mt < 2; mt++) {
                int base = (warpM * 32 + mt * 16 + r4) * 36;
                ah[mt][0] = AH[base + klo];
                ah[mt][1] = AH[base + 8 * 36 + klo];
                ah[mt][2] = AH[base + klo + 4];
                ah[mt][3] = AH[base + 8 * 36 + klo + 4];
                al[mt][0] = AL[base + klo];
                al[mt][1] = AL[base + 8 * 36 + klo];
                al[mt][2] = AL[base + klo + 4];
                al[mt][3] = AL[base + 8 * 36 + klo + 4];
            }
#pragma unroll
            for (int nt = 0; nt < 8; nt++) {
                int nB = warpN * 64 + nt * 8 + r4;
                uint32_t bh0 = BH[klo * 136 + nB];
                uint32_t bh1 = BH[(klo + 4) * 136 + nB];
                uint32_t bl0 = BL[klo * 136 + nB];
                uint32_t bl1 = BL[(klo + 4) * 136 + nB];
#pragma unroll
                for (int mt = 0; mt < 2; mt++) {
                    mma16816(acc[mt][nt], ah[mt], bh0, bh1);
                    mma16816(acc[mt][nt], ah[mt], bl0, bl1);
                    mma16816(acc[mt][nt], al[mt], bh0, bh1);
                }
            }
        }
    }

#pragma unroll
    for (int mt = 0; mt < 2; mt++) {
        int rowA = row0 + warpM * 32 + mt * 16 + r4;
        int rowB = rowA + 8;
#pragma unroll
        for (int nt = 0; nt < 8; nt++) {
            int col = warpN * 64 + nt * 8 + q4 * 2;
            if (rowA < M)
                *reinterpret_cast<__half2*>(C + (size_t)rowA * 128 + col) =
                    __floats2half2_rn(acc[mt][nt][0], acc[mt][nt][1]);
            if (rowB < M)
                *reinterpret_cast<__half2*>(C + (size_t)rowB * 128 + col) =
                    __floats2half2_rn(acc[mt][nt][2], acc[mt][nt][3]);
        }
    }
}

// ===========================================================================
// CSR build: histogram -> self-zeroing scan -> offset-apply -> scatter (x8)
// ===========================================================================
__global__ void hist_dst4(const int4* __restrict__ dst4, int* __restrict__ cnt, int n4) {
    int e = blockIdx.x * blockDim.x + threadIdx.x;
    if (e >= n4) return;
    int4 d = __ldg(dst4 + e);
    atomicAdd(&cnt[d.x], 1);
    atomicAdd(&cnt[d.y], 1);
    atomicAdd(&cnt[d.z], 1);
    atomicAdd(&cnt[d.w], 1);
}

// Reads cnt, zeroes it (restores invariant cnt==0 for the next replay).
__global__ void scan_p1(int* __restrict__ cnt, int* __restrict__ tmp,
                        int* __restrict__ bsum, int n) {
    __shared__ int wsum[8];
    const int lane = threadIdx.x & 31;
    const int wid  = threadIdx.x >> 5;
    int i = blockIdx.x * 256 + threadIdx.x;
    int v = 0;
    if (i < n) { v = cnt[i]; cnt[i] = 0; }
    int incl = v;
#pragma unroll
    for (int o = 1; o < 32; o <<= 1) {
        int tt = __shfl_up_sync(0xffffffffu, incl, o);
        if (lane >= o) incl += tt;
    }
    if (lane == 31) wsum[wid] = incl;
    __syncthreads();
    if (wid == 0) {
        int s = (lane < 8) ? wsum[lane] : 0;
#pragma unroll
        for (int o = 1; o < 8; o <<= 1) {
            int tt = __shfl_up_sync(0xffffffffu, s, o);
            if (lane >= o) s += tt;
        }
        if (lane < 8) wsum[lane] = s;
    }
    __syncthreads();
    int excl = (wid ? wsum[wid - 1] : 0) + incl - v;
    if (i < n) tmp[i] = excl;
    if (threadIdx.x == 255) bsum[blockIdx.x] = excl + v;
}

__global__ void scan_p3(const int* __restrict__ tmp, const int* __restrict__ bsum,
                        int* __restrict__ rp, int* __restrict__ cursor,
                        int n, int nb, int nE) {
    __shared__ int red[8];
    const int lane = threadIdx.x & 31;
    const int wid  = threadIdx.x >> 5;
    int v = (threadIdx.x < nb && threadIdx.x < blockIdx.x) ? __ldg(bsum + threadIdx.x) : 0;
#pragma unroll
    for (int o = 16; o > 0; o >>= 1) v += __shfl_xor_sync(0xffffffffu, v, o);
    if (lane == 0) red[wid] = v;
    __syncthreads();
    if (threadIdx.x == 0) {
        int s = 0;
#pragma unroll
        for (int j = 0; j < 8; j++) s += red[j];
        red[0] = s;
    }
    __syncthreads();
    int off = red[0];
    int i = blockIdx.x * 256 + threadIdx.x;
    if (i < n) {
        int val = tmp[i] + off;
        rp[i] = val;
        cursor[i] = val;
    }
    if (blockIdx.x == 0 && threadIdx.x == 0) rp[n] = nE;
}

// 8 edges per thread: more outstanding atomics (scatter is latency-bound).
__global__ void scatter_edges8(const int* __restrict__ src, const int* __restrict__ dst,
                               const float* __restrict__ w, int* __restrict__ cursor,
                               int2* __restrict__ pe, int nE) {
    int i = blockIdx.x * blockDim.x + threadIdx.x;
    int e0 = i * 8;
    if (e0 + 8 <= nE) {
        int4 sA = __ldg((const int4*)(src + e0));
        int4 sB = __ldg((const int4*)(src + e0 + 4));
        int4 dA = __ldg((const int4*)(dst + e0));
        int4 dB = __ldg((const int4*)(dst + e0 + 4));
        float4 wA = __ldg((const float4*)(w + e0));
        float4 wB = __ldg((const float4*)(w + e0 + 4));
        // Issue all 8 atomics back-to-back, then all stores.
        int p0 = atomicAdd(&cursor[dA.x], 1);
        int p1 = atomicAdd(&cursor[dA.y], 1);
        int p2 = atomicAdd(&cursor[dA.z], 1);
        int p3 = atomicAdd(&cursor[dA.w], 1);
        int p4 = atomicAdd(&cursor[dB.x], 1);
        int p5 = atomicAdd(&cursor[dB.y], 1);
        int p6 = atomicAdd(&cursor[dB.z], 1);
        int p7 = atomicAdd(&cursor[dB.w], 1);
        pe[p0] = make_int2(sA.x, __float_as_int(wA.x));
        pe[p1] = make_int2(sA.y, __float_as_int(wA.y));
        pe[p2] = make_int2(sA.z, __float_as_int(wA.z));
        pe[p3] = make_int2(sA.w, __float_as_int(wA.w));
        pe[p4] = make_int2(sB.x, __float_as_int(wB.x));
        pe[p5] = make_int2(sB.y, __float_as_int(wB.y));
        pe[p6] = make_int2(sB.z, __float_as_int(wB.z));
        pe[p7] = make_int2(sB.w, __float_as_int(wB.w));
    } else {
        for (int e = e0; e < nE; e++) {
            int dd = __ldg(dst + e);
            int pos = atomicAdd(&cursor[dd], 1);
            pe[pos] = make_int2(__ldg(src + e), __float_as_int(__ldg(w + e)));
        }
    }
}

// ===========================================================================
// GEMM3: C[M,40] = H[M,128] @ W2[128,40]; fp16 in, fp16 out; fp32 math.
// ===========================================================================
__global__ void sgemm40(const __half* __restrict__ H, const float* __restrict__ W,
                        __half* __restrict__ C, int M) {
    __shared__ float Ht[32][132];
    __shared__ float Ws[128][40];

    const int t = threadIdx.x;
    const int row0 = blockIdx.x * 32;

#pragma unroll
    for (int l = 0; l < 4; l++) {
        int q = t + l * 256;
        int r = q >> 5;
        int c4 = q & 31;
        float4 v = make_float4(0.f, 0.f, 0.f, 0.f);
        if (row0 + r < M)
            v = load4f(H + (size_t)(row0 + r) * 128 + c4 * 4);
        *reinterpret_cast<float4*>(&Ht[r][c4 * 4]) = v;
    }
#pragma unroll
    for (int l = 0; l < 20; l++) {
        int q = t + l * 256;
        Ws[q / 40][q % 40] = W[q];
    }
    __syncthreads();

    const int r = t >> 3;
    const int cg = t & 7;
    float acc[5] = {0.f, 0.f, 0.f, 0.f, 0.f};
#pragma unroll 8
    for (int k = 0; k < 128; k++) {
        float h = Ht[r][k];
#pragma unroll
        for (int j = 0; j < 5; j++)
            acc[j] = fmaf(h, Ws[k][cg * 5 + j], acc[j]);
    }
    int grow = row0 + r;
    if (grow < M) {
#pragma unroll
        for (int j = 0; j < 5; j++)
            C[(size_t)grow * 40 + cg * 5 + j] = __float2half_rn(acc[j]);
    }
}

// ===========================================================================
// Gather SpMM (feat=128, fp16 in, fp32 accum, fp16 out) + bias + ReLU
// ===========================================================================
__device__ __forceinline__ void acc4h(float& ax, float& ay, float& az, float& aw,
                                      float w, uint2 r) {
    float2 a01 = __half22float2(*reinterpret_cast<__half2*>(&r.x));
    float2 a23 = __half22float2(*reinterpret_cast<__half2*>(&r.y));
    ax = fmaf(w, a01.x, ax); ay = fmaf(w, a01.y, ay);
    az = fmaf(w, a23.x, az); aw = fmaf(w, a23.y, aw);
}

__global__ void __launch_bounds__(256) spmm_csr128h(
    const __half* __restrict__ H, const int* __restrict__ rp,
    const int2* __restrict__ pe, const float* __restrict__ bias,
    __half* __restrict__ out, int M) {
    int row = blockIdx.x * 8 + (threadIdx.x >> 5);
    int lane = threadIdx.x & 31;
    if (row >= M) return;
    int p  = __ldg(rp + row);
    int pend = __ldg(rp + row + 1);

    const char* Hb = reinterpret_cast<const char*>(H) + lane * 8;
    float ax = 0.f, ay = 0.f, az = 0.f, aw = 0.f;

    for (; p + 4 <= pend; p += 4) {
        int2 e0 = __ldg(pe + p + 0), e1 = __ldg(pe + p + 1);
        int2 e2 = __ldg(pe + p + 2), e3 = __ldg(pe + p + 3);
        uint2 r0 = *reinterpret_cast<const uint2*>(Hb + (size_t)e0.x * 256);
        uint2 r1 = *reinterpret_cast<const uint2*>(Hb + (size_t)e1.x * 256);
        uint2 r2 = *reinterpret_cast<const uint2*>(Hb + (size_t)e2.x * 256);
        uint2 r3 = *reinterpret_cast<const uint2*>(Hb + (size_t)e3.x * 256);
        acc4h(ax, ay, az, aw, __int_as_float(e0.y), r0);
        acc4h(ax, ay, az, aw, __int_as_float(e1.y), r1);
        acc4h(ax, ay, az, aw, __int_as_float(e2.y), r2);
        acc4h(ax, ay, az, aw, __int_as_float(e3.y), r3);
    }
    for (; p < pend; p++) {
        int2 e = __ldg(pe + p);
        uint2 r0 = *reinterpret_cast<const uint2*>(Hb + (size_t)e.x * 256);
        acc4h(ax, ay, az, aw, __int_as_float(e.y), r0);
    }

    float4 b4 = *reinterpret_cast<const float4*>(bias + lane * 4);
    __half2 o01 = __floats2half2_rn(fmaxf(ax + b4.x, 0.f), fmaxf(ay + b4.y, 0.f));
    __half2 o23 = __floats2half2_rn(fmaxf(az + b4.z, 0.f), fmaxf(aw + b4.w, 0.f));
    uint2 st;
    st.x = *reinterpret_cast<uint32_t*>(&o01);
    st.y = *reinterpret_cast<uint32_t*>(&o23);
    *reinterpret_cast<uint2*>(reinterpret_cast<char*>(out) + (size_t)row * 256 + lane * 8) = st;
}

// ===========================================================================
// Gather SpMM (feat=40, fp16 logits, fp32 accum) + bias + log_softmax
// ===========================================================================
__global__ void __launch_bounds__(256) spmm_csr40_lsm(
    const __half* __restrict__ C, const int* __restrict__ rp,
    const int2* __restrict__ pe, const float* __restrict__ b,
    float* __restrict__ out, int M) {
    int row = blockIdx.x * 8 + (threadIdx.x >> 5);
    int lane = threadIdx.x & 31;
    if (row >= M) return;
    int p  = __ldg(rp + row);
    int pend = __ldg(rp + row + 1);

    float a0 = 0.f, a1 = 0.f;
    for (; p + 2 <= pend; p += 2) {
        int2 e0 = __ldg(pe + p), e1 = __ldg(pe + p + 1);
        float w0 = __int_as_float(e0.y), w1 = __int_as_float(e1.y);
        const __half* c0 = C + (size_t)e0.x * 40;
        const __half* c1 = C + (size_t)e1.x * 40;
        float x0 = __half2float(__ldg(c0 + lane));
        float x1 = __half2float(__ldg(c1 + lane));
        float y0 = (lane < 8) ? __half2float(__ldg(c0 + 32 + lane)) : 0.f;
        float y1 = (lane < 8) ? __half2float(__ldg(c1 + 32 + lane)) : 0.f;
        a0 = fmaf(w0, x0, a0); a0 = fmaf(w1, x1, a0);
        a1 = fmaf(w0, y0, a1); a1 = fmaf(w1, y1, a1);
    }
    if (p < pend) {
        int2 e = __ldg(pe + p);
        float w = __int_as_float(e.y);
        const __half* c0 = C + (size_t)e.x * 40;
        a0 = fmaf(w, __half2float(__ldg(c0 + lane)), a0);
        if (lane < 8) a1 = fmaf(w, __half2float(__ldg(c0 + 32 + lane)), a1);
    }

    float v0 = a0 + __ldg(b + lane);
    float v1 = (lane < 8) ? (a1 + __ldg(b + 32 + lane)) : -INFINITY;

    float m = fmaxf(v0, v1);
#pragma unroll
    for (int o = 16; o > 0; o >>= 1) m = fmaxf(m, __shfl_xor_sync(0xffffffffu, m, o));
    float s = __expf(v0 - m) + ((lane < 8) ? __expf(v1 - m) : 0.f);
#pragma unroll
    for (int o = 16; o > 0; o >>= 1) s += __shfl_xor_sync(0xffffffffu, s, o);
    float ls = m + __logf(s);

    out[(size_t)row * 40 + lane] = v0 - ls;
    if (lane < 8) out[(size_t)row * 40 + 32 + lane] = v1 - ls;
}

// ===========================================================================
extern "C" void kernel_launch(void* const* d_in, const int* in_sizes, int n_in,
                              void* d_out, int out_size) {
    const float* x    = (const float*)d_in[0];
    const int*   esrc = (const int*)  d_in[1];
    const int*   edst = (const int*)  d_in[2];
    const float* ew   = (const float*)d_in[3];
    const float* W1   = (const float*)d_in[4];
    const float* b1   = (const float*)d_in[5];
    const float* Wh   = (const float*)d_in[6];
    const float* bh   = (const float*)d_in[7];
    const float* W2   = (const float*)d_in[8];
    const float* b2   = (const float*)d_in[9];
    float* out = (float*)d_out;

    const int M  = in_sizes[0] / NFEAT;   // 50000
    const int nE = in_sizes[1];           // 1600000

    __half *Ah, *Bh, *Ch;
    int *cnt, *cursor, *rp, *tmp, *bsum;
    int2 *pe;
    uint32_t *W1h, *W1l, *Whh, *Whl;
    cudaGetSymbolAddress((void**)&Ah, g_Ah);
    cudaGetSymbolAddress((void**)&Bh, g_Bh);
    cudaGetSymbolAddress((void**)&Ch, g_Ch);
    cudaGetSymbolAddress((void**)&cnt, g_cnt);
    cudaGetSymbolAddress((void**)&cursor, g_cursor);
    cudaGetSymbolAddress((void**)&rp, g_rp);
    cudaGetSymbolAddress((void**)&tmp, g_tmp);
    cudaGetSymbolAddress((void**)&bsum, g_bsum);
    cudaGetSymbolAddress((void**)&pe, g_pe);
    cudaGetSymbolAddress((void**)&W1h, g_W1h);
    cudaGetSymbolAddress((void**)&W1l, g_W1l);
    cudaGetSymbolAddress((void**)&Whh, g_Whh);
    cudaGetSymbolAddress((void**)&Whl, g_Whl);

    static cudaStream_t s2 = nullptr;
    static cudaEvent_t evF = nullptr, evJ = nullptr;
    if (!s2) {
        cudaStreamCreateWithFlags(&s2, cudaStreamNonBlocking);
        cudaEventCreateWithFlags(&evF, cudaEventDisableTiming);
        cudaEventCreateWithFlags(&evJ, cudaEventDisableTiming);
        cudaFuncSetAttribute(mma_gemm128<float>,
                             cudaFuncAttributeMaxDynamicSharedMemorySize, SM_U32 * 4);
        cudaFuncSetAttribute(mma_gemm128<__half>,
                             cudaFuncAttributeMaxDynamicSharedMemorySize, SM_U32 * 4);
    }

    const int nb = (M + 255) / 256;           // 196
    const int gemmBlocks = (M + 127) / 128;   // 391
    const int spmmBlocks = (M + 7) / 8;
    const int nE8 = (nE + 7) / 8;

    // ---- Fork: CSR build on s2 (cnt==0 by invariant), main: weights + GEMM1
    cudaEventRecord(evF, 0);
    cudaStreamWaitEvent(s2, evF, 0);

    hist_dst4<<<((nE / 4) + 255) / 256, 256, 0, s2>>>((const int4*)edst, cnt, nE / 4);
    scan_p1<<<nb, 256, 0, s2>>>(cnt, tmp, bsum, M);
    scan_p3<<<nb, 256, 0, s2>>>(tmp, bsum, rp, cursor, M, nb, nE);
    scatter_edges8<<<(nE8 + 255) / 256, 256, 0, s2>>>(esrc, edst, ew, cursor, pe, nE);
    cudaEventRecord(evJ, s2);

    conv_weights<<<160, 256>>>(W1, Wh, W1h, W1l, Whh, Whl);
    mma_gemm128<float><<<gemmBlocks, 256, SM_U32 * 4>>>(x, W1h, W1l, Ah, M, NFEAT);

    cudaStreamWaitEvent(0, evJ, 0);   // join

    // Layer 1 aggregation (fp16 out)
    spmm_csr128h<<<spmmBlocks, 256>>>(Ah, rp, pe, b1, Bh, M);

    // Layer 2 (fp16 in)
    mma_gemm128<__half><<<gemmBlocks, 256, SM_U32 * 4>>>(Bh, Whh, Whl, Ah, M, NHID);
    spmm_csr128h<<<spmmBlocks, 256>>>(Ah, rp, pe, bh, Bh, M);

    // Layer 3 + log_softmax
    sgemm40<<<(M + 31) / 32, 256>>>(Bh, W2, Ch, M);
    spmm_csr40_lsm<<<spmmBlocks, 256>>>(Ch, rp, pe, b2, out, M);
}

// round 13
// speedup vs baseline: 2.0053x; 1.0414x over previous
#include <cuda_runtime.h>
#include <cuda_bf16.h>
#include <cuda_fp16.h>
#include <math.h>
#include <cstdint>

// ---------------------------------------------------------------------------
// GCN: 3x { H = A_sparse @ (H @ W) + b (,ReLU) } -> log_softmax
// N=50000, E=1.6M, 512 -> 128 -> 128 -> 40
// Round 13: exact R9 structure (best: 275.7) + 4-byte packed edge records
//           (u16 src | fp16 weight) halving edge traffic everywhere.
// ---------------------------------------------------------------------------

#define NNODES 50000
#define NEDGES 1600000
#define NFEAT 512
#define NHID  128
#define NCLASS 40

// Scratch (__device__ globals; no allocations allowed)
__device__ __half g_Ah[NNODES * NHID];   // GEMM output / spmm input
__device__ __half g_Bh[NNODES * NHID];   // spmm output / GEMM input
__device__ __half g_Ch[NNODES * NCLASS]; // GEMM3 output (fp16 logits)
__device__ int    g_cnt[NNODES];
__device__ int    g_cursor[NNODES];
__device__ int    g_rp[NNODES + 1];
__device__ int    g_tmp[NNODES];
__device__ int    g_bsum[256];
__device__ uint32_t g_pe[NEDGES];        // packed (fp16 w << 16 | u16 src)
// Pre-packed weights: bf16x2 k-pairs, layout [k2][n] (n=128)
__device__ uint32_t g_W1h[256 * 128];
__device__ uint32_t g_W1l[256 * 128];
__device__ uint32_t g_Whh[64 * 128];
__device__ uint32_t g_Whl[64 * 128];

// ===========================================================================
// helpers
// ===========================================================================
__device__ __forceinline__ void cvt_hilo(float x, float y, uint32_t& hi, uint32_t& lo) {
    __nv_bfloat16 hx = __float2bfloat16(x);
    __nv_bfloat16 hy = __float2bfloat16(y);
    float rx = x - __bfloat162float(hx);
    float ry = y - __bfloat162float(hy);
    __nv_bfloat162 H; H.x = hx; H.y = hy;
    __nv_bfloat162 L; L.x = __float2bfloat16(rx); L.y = __float2bfloat16(ry);
    hi = *reinterpret_cast<uint32_t*>(&H);
    lo = *reinterpret_cast<uint32_t*>(&L);
}

__device__ __forceinline__ void mma16816(float* d, const uint32_t* a, uint32_t b0, uint32_t b1) {
    asm volatile(
        "mma.sync.aligned.m16n8k16.row.col.f32.bf16.bf16.f32 "
        "{%0,%1,%2,%3}, {%4,%5,%6,%7}, {%8,%9}, {%0,%1,%2,%3};"
        : "+f"(d[0]), "+f"(d[1]), "+f"(d[2]), "+f"(d[3])
        : "r"(a[0]), "r"(a[1]), "r"(a[2]), "r"(a[3]), "r"(b0), "r"(b1));
}

__device__ __forceinline__ float4 load4f(const float* p) {
    return *reinterpret_cast<const float4*>(p);
}
__device__ __forceinline__ float4 load4f(const __half* p) {
    uint2 u = *reinterpret_cast<const uint2*>(p);
    float2 a = __half22float2(*reinterpret_cast<__half2*>(&u.x));
    float2 b = __half22float2(*reinterpret_cast<__half2*>(&u.y));
    return make_float4(a.x, a.y, b.x, b.y);
}

// Unpack edge record: low 16 = src, high 16 = fp16 weight
__device__ __forceinline__ void unpack_edge(uint32_t rec, int& s, float& w) {
    s = (int)(rec & 0xFFFFu);
    w = __half2float(__ushort_as_half((unsigned short)(rec >> 16)));
}

// SMEM layout (u32 units). A tiles: [m=128][k2=32 + pad4]. B: [k2=32][n=128+8].
#define AH_OFF 0
#define AL_OFF 4608
#define BH_OFF 9216
#define BL_OFF 13568
#define SM_U32 17920   // 71680 bytes

// ===========================================================================
// Weight pre-pack: W[K][128] fp32 -> hi/lo bf16x2 planes [K/2][128]
// ===========================================================================
__global__ void conv_weights(const float* __restrict__ W1, const float* __restrict__ Wh,
                             uint32_t* __restrict__ W1h, uint32_t* __restrict__ W1l,
                             uint32_t* __restrict__ Whh, uint32_t* __restrict__ Whl) {
    int i = blockIdx.x * 256 + threadIdx.x;
    if (i < 256 * 128) {
        int k2 = i >> 7, n = i & 127;
        float v0 = __ldg(W1 + (size_t)(2 * k2) * 128 + n);
        float v1 = __ldg(W1 + (size_t)(2 * k2 + 1) * 128 + n);
        uint32_t h, lo;
        cvt_hilo(v0, v1, h, lo);
        W1h[i] = h; W1l[i] = lo;
    } else if (i < 256 * 128 + 64 * 128) {
        int j = i - 256 * 128;
        int k2 = j >> 7, n = j & 127;
        float v0 = __ldg(Wh + (size_t)(2 * k2) * 128 + n);
        float v1 = __ldg(Wh + (size_t)(2 * k2 + 1) * 128 + n);
        uint32_t h, lo;
        cvt_hilo(v0, v1, h, lo);
        Whh[j] = h; Whl[j] = lo;
    }
}

// ===========================================================================
// mma.sync GEMM: C[M,128] = A[M,K] @ W[K,128]; A fp32/fp16; W pre-packed.
// bf16 hi/lo split, fp32 accumulate, fp16 out. CTA 128x128, 8 warps.
// ===========================================================================
template <typename TIn>
__global__ void __launch_bounds__(256, 2) mma_gemm128(
    const TIn* __restrict__ A,
    const uint32_t* __restrict__ Wph, const uint32_t* __restrict__ Wpl,
    __half* __restrict__ C, int M, int K) {
    extern __shared__ uint32_t sm[];
    uint32_t* AH = sm + AH_OFF;
    uint32_t* AL = sm + AL_OFF;
    uint32_t* BH = sm + BH_OFF;
    uint32_t* BL = sm + BL_OFF;

    const int t = threadIdx.x;
    const int lane = t & 31;
    const int wid = t >> 5;
    const int warpM = wid >> 1;
    const int warpN = wid & 1;
    const int row0 = blockIdx.x * 128;

    float acc[2][8][4];
#pragma unroll
    for (int mt = 0; mt < 2; mt++)
#pragma unroll
        for (int nt = 0; nt < 8; nt++)
#pragma unroll
            for (int e = 0; e < 4; e++) acc[mt][nt][e] = 0.f;

    const int r4 = lane >> 2;
    const int q4 = lane & 3;

    const int nChunks = K >> 6;
    for (int c = 0; c < nChunks; c++) {
        const int k0 = c << 6;
        const int k0h = c << 5;
        __syncthreads();

#pragma unroll
        for (int l = 0; l < 8; l++) {
            int q = t + l * 256;
            int m = q >> 4;
            int c4 = q & 15;
            float4 v = make_float4(0.f, 0.f, 0.f, 0.f);
            if (row0 + m < M)
                v = load4f(A + (size_t)(row0 + m) * K + k0 + c4 * 4);
            uint32_t h0, l0, h1, l1;
            cvt_hilo(v.x, v.y, h0, l0);
            cvt_hilo(v.z, v.w, h1, l1);
            int base = m * 36 + c4 * 2;
            AH[base] = h0; AH[base + 1] = h1;
            AL[base] = l0; AL[base + 1] = l1;
        }
#pragma unroll
        for (int l = 0; l < 4; l++) {
            int q = t + l * 256;
            int k2 = q >> 5;
            int n4 = q & 31;
            size_t goff = (size_t)(k0h + k2) * 128 + n4 * 4;
            uint4 vh = __ldg(reinterpret_cast<const uint4*>(Wph + goff));
            uint4 vl = __ldg(reinterpret_cast<const uint4*>(Wpl + goff));
            *reinterpret_cast<uint4*>(&BH[k2 * 136 + n4 * 4]) = vh;
            *reinterpret_cast<uint4*>(&BL[k2 * 136 + n4 * 4]) = vl;
        }
        __syncthreads();

#pragma unroll
        for (int k8 = 0; k8 < 4; k8++) {
            int klo = k8 * 8 + q4;
            uint32_t ah[2][4], al[2][4];
#pragma unroll
            for (int mt = 0; mt < 2; mt++) {
                int base = (warpM * 32 + mt * 16 + r4) * 36;
                ah[mt][0] = AH[base + klo];
                ah[mt][1] = AH[base + 8 * 36 + klo];
                ah[mt][2] = AH[base + klo + 4];
                ah[mt][3] = AH[base + 8 * 36 + klo + 4];
                al[mt][0] = AL[base + klo];
                al[mt][1] = AL[base + 8 * 36 + klo];
                al[mt][2] = AL[base + klo + 4];
                al[mt][3] = AL[base + 8 * 36 + klo + 4];
            }
#pragma unroll
            for (int nt = 0; nt < 8; nt++) {
                int nB = warpN * 64 + nt * 8 + r4;
                uint32_t bh0 = BH[klo * 136 + nB];
                uint32_t bh1 = BH[(klo + 4) * 136 + nB];
                uint32_t bl0 = BL[klo * 136 + nB];
                uint32_t bl1 = BL[(klo + 4) * 136 + nB];
#pragma unroll
                for (int mt = 0; mt < 2; mt++) {
                    mma16816(acc[mt][nt], ah[mt], bh0, bh1);
                    mma16816(acc[mt][nt], ah[mt], bl0, bl1);
                    mma16816(acc[mt][nt], al[mt], bh0, bh1);
                }
            }
        }
    }

#pragma unroll
    for (int mt = 0; mt < 2; mt++) {
        int rowA = row0 + warpM * 32 + mt * 16 + r4;
        int rowB = rowA + 8;
#pragma unroll
        for (int nt = 0; nt < 8; nt++) {
            int col = warpN * 64 + nt * 8 + q4 * 2;
            if (rowA < M)
                *reinterpret_cast<__half2*>(C + (size_t)rowA * 128 + col) =
                    __floats2half2_rn(acc[mt][nt][0], acc[mt][nt][1]);
            if (rowB < M)
                *reinterpret_cast<__half2*>(C + (size_t)rowB * 128 + col) =
                    __floats2half2_rn(acc[mt][nt][2], acc[mt][nt][3]);
        }
    }
}

// ===========================================================================
// CSR build: zero -> histogram -> 2-kernel scan -> scatter (4 edges/thread)
// ===========================================================================
__global__ void zero_int4(int4* p, int n4) {
    int i = blockIdx.x * blockDim.x + threadIdx.x;
    if (i < n4) p[i] = make_int4(0, 0, 0, 0);
}

__global__ void hist_dst4(const int4* __restrict__ dst4, int* __restrict__ cnt, int n4) {
    int e = blockIdx.x * blockDim.x + threadIdx.x;
    if (e >= n4) return;
    int4 d = __ldg(dst4 + e);
    atomicAdd(&cnt[d.x], 1);
    atomicAdd(&cnt[d.y], 1);
    atomicAdd(&cnt[d.z], 1);
    atomicAdd(&cnt[d.w], 1);
}

__global__ void scan_p1(const int* __restrict__ cnt, int* __restrict__ tmp,
                        int* __restrict__ bsum, int n) {
    __shared__ int wsum[8];
    const int lane = threadIdx.x & 31;
    const int wid  = threadIdx.x >> 5;
    int i = blockIdx.x * 256 + threadIdx.x;
    int v = (i < n) ? cnt[i] : 0;
    int incl = v;
#pragma unroll
    for (int o = 1; o < 32; o <<= 1) {
        int tt = __shfl_up_sync(0xffffffffu, incl, o);
        if (lane >= o) incl += tt;
    }
    if (lane == 31) wsum[wid] = incl;
    __syncthreads();
    if (wid == 0) {
        int s = (lane < 8) ? wsum[lane] : 0;
#pragma unroll
        for (int o = 1; o < 8; o <<= 1) {
            int tt = __shfl_up_sync(0xffffffffu, s, o);
            if (lane >= o) s += tt;
        }
        if (lane < 8) wsum[lane] = s;
    }
    __syncthreads();
    int excl = (wid ? wsum[wid - 1] : 0) + incl - v;
    if (i < n) tmp[i] = excl;
    if (threadIdx.x == 255) bsum[blockIdx.x] = excl + v;
}

__global__ void scan_p3(const int* __restrict__ tmp, const int* __restrict__ bsum,
                        int* __restrict__ rp, int* __restrict__ cursor,
                        int n, int nb, int nE) {
    __shared__ int red[8];
    const int lane = threadIdx.x & 31;
    const int wid  = threadIdx.x >> 5;
    int v = (threadIdx.x < nb && threadIdx.x < blockIdx.x) ? __ldg(bsum + threadIdx.x) : 0;
#pragma unroll
    for (int o = 16; o > 0; o >>= 1) v += __shfl_xor_sync(0xffffffffu, v, o);
    if (lane == 0) red[wid] = v;
    __syncthreads();
    if (threadIdx.x == 0) {
        int s = 0;
#pragma unroll
        for (int j = 0; j < 8; j++) s += red[j];
        red[0] = s;
    }
    __syncthreads();
    int off = red[0];
    int i = blockIdx.x * 256 + threadIdx.x;
    if (i < n) {
        int val = tmp[i] + off;
        rp[i] = val;
        cursor[i] = val;
    }
    if (blockIdx.x == 0 && threadIdx.x == 0) rp[n] = nE;
}

__global__ void scatter_edges4(const int* __restrict__ src, const int* __restrict__ dst,
                               const float* __restrict__ w, int* __restrict__ cursor,
                               uint32_t* __restrict__ pe, int nE) {
    int i = blockIdx.x * blockDim.x + threadIdx.x;
    int e0 = i * 4;
    if (e0 + 4 <= nE) {
        int4 s = __ldg((const int4*)(src + e0));
        int4 d = __ldg((const int4*)(dst + e0));
        float4 ww = __ldg((const float4*)(w + e0));
        uint32_t r0 = (uint32_t)s.x | ((uint32_t)__half_as_ushort(__float2half_rn(ww.x)) << 16);
        uint32_t r1 = (uint32_t)s.y | ((uint32_t)__half_as_ushort(__float2half_rn(ww.y)) << 16);
        uint32_t r2 = (uint32_t)s.z | ((uint32_t)__half_as_ushort(__float2half_rn(ww.z)) << 16);
        uint32_t r3 = (uint32_t)s.w | ((uint32_t)__half_as_ushort(__float2half_rn(ww.w)) << 16);
        int p0 = atomicAdd(&cursor[d.x], 1);
        pe[p0] = r0;
        int p1 = atomicAdd(&cursor[d.y], 1);
        pe[p1] = r1;
        int p2 = atomicAdd(&cursor[d.z], 1);
        pe[p2] = r2;
        int p3 = atomicAdd(&cursor[d.w], 1);
        pe[p3] = r3;
    } else {
        for (int e = e0; e < nE; e++) {
            int dd = __ldg(dst + e);
            int pos = atomicAdd(&cursor[dd], 1);
            pe[pos] = (uint32_t)__ldg(src + e) |
                      ((uint32_t)__half_as_ushort(__float2half_rn(__ldg(w + e))) << 16);
        }
    }
}

// ===========================================================================
// GEMM3: C[M,40] = H[M,128] @ W2[128,40]; fp16 in, fp16 out; fp32 math.
// ===========================================================================
__global__ void sgemm40(const __half* __restrict__ H, const float* __restrict__ W,
                        __half* __restrict__ C, int M) {
    __shared__ float Ht[32][132];
    __shared__ float Ws[128][40];

    const int t = threadIdx.x;
    const int row0 = blockIdx.x * 32;

#pragma unroll
    for (int l = 0; l < 4; l++) {
        int q = t + l * 256;
        int r = q >> 5;
        int c4 = q & 31;
        float4 v = make_float4(0.f, 0.f, 0.f, 0.f);
        if (row0 + r < M)
            v = load4f(H + (size_t)(row0 + r) * 128 + c4 * 4);
        *reinterpret_cast<float4*>(&Ht[r][c4 * 4]) = v;
    }
#pragma unroll
    for (int l = 0; l < 20; l++) {
        int q = t + l * 256;
        Ws[q / 40][q % 40] = W[q];
    }
    __syncthreads();

    const int r = t >> 3;
    const int cg = t & 7;
    float acc[5] = {0.f, 0.f, 0.f, 0.f, 0.f};
#pragma unroll 8
    for (int k = 0; k < 128; k++) {
        float h = Ht[r][k];
#pragma unroll
        for (int j = 0; j < 5; j++)
            acc[j] = fmaf(h, Ws[k][cg * 5 + j], acc[j]);
    }
    int grow = row0 + r;
    if (grow < M) {
#pragma unroll
        for (int j = 0; j < 5; j++)
            C[(size_t)grow * 40 + cg * 5 + j] = __float2half_rn(acc[j]);
    }
}

// ===========================================================================
// Gather SpMM (feat=128, fp16 in, fp32 accum, fp16 out) + bias + ReLU
// ===========================================================================
__device__ __forceinline__ void acc4h(float& ax, float& ay, float& az, float& aw,
                                      float w, uint2 r) {
    float2 a01 = __half22float2(*reinterpret_cast<__half2*>(&r.x));
    float2 a23 = __half22float2(*reinterpret_cast<__half2*>(&r.y));
    ax = fmaf(w, a01.x, ax); ay = fmaf(w, a01.y, ay);
    az = fmaf(w, a23.x, az); aw = fmaf(w, a23.y, aw);
}

__global__ void __launch_bounds__(256) spmm_csr128h(
    const __half* __restrict__ H, const int* __restrict__ rp,
    const uint32_t* __restrict__ pe, const float* __restrict__ bias,
    __half* __restrict__ out, int M) {
    int row = blockIdx.x * 8 + (threadIdx.x >> 5);
    int lane = threadIdx.x & 31;
    if (row >= M) return;
    int p  = __ldg(rp + row);
    int pend = __ldg(rp + row + 1);

    const char* Hb = reinterpret_cast<const char*>(H) + lane * 8;
    float ax = 0.f, ay = 0.f, az = 0.f, aw = 0.f;

    for (; p + 4 <= pend; p += 4) {
        uint32_t e0 = __ldg(pe + p + 0), e1 = __ldg(pe + p + 1);
        uint32_t e2 = __ldg(pe + p + 2), e3 = __ldg(pe + p + 3);
        int s0, s1, s2, s3;
        float w0, w1, w2, w3;
        unpack_edge(e0, s0, w0);
        unpack_edge(e1, s1, w1);
        unpack_edge(e2, s2, w2);
        unpack_edge(e3, s3, w3);
        uint2 r0 = *reinterpret_cast<const uint2*>(Hb + (size_t)s0 * 256);
        uint2 r1 = *reinterpret_cast<const uint2*>(Hb + (size_t)s1 * 256);
        uint2 r2 = *reinterpret_cast<const uint2*>(Hb + (size_t)s2 * 256);
        uint2 r3 = *reinterpret_cast<const uint2*>(Hb + (size_t)s3 * 256);
        acc4h(ax, ay, az, aw, w0, r0);
        acc4h(ax, ay, az, aw, w1, r1);
        acc4h(ax, ay, az, aw, w2, r2);
        acc4h(ax, ay, az, aw, w3, r3);
    }
    for (; p < pend; p++) {
        int s;
        float w;
        unpack_edge(__ldg(pe + p), s, w);
        uint2 r0 = *reinterpret_cast<const uint2*>(Hb + (size_t)s * 256);
        acc4h(ax, ay, az, aw, w, r0);
    }

    float4 b4 = *reinterpret_cast<const float4*>(bias + lane * 4);
    __half2 o01 = __floats2half2_rn(fmaxf(ax + b4.x, 0.f), fmaxf(ay + b4.y, 0.f));
    __half2 o23 = __floats2half2_rn(fmaxf(az + b4.z, 0.f), fmaxf(aw + b4.w, 0.f));
    uint2 st;
    st.x = *reinterpret_cast<uint32_t*>(&o01);
    st.y = *reinterpret_cast<uint32_t*>(&o23);
    *reinterpret_cast<uint2*>(reinterpret_cast<char*>(out) + (size_t)row * 256 + lane * 8) = st;
}

// ===========================================================================
// Gather SpMM (feat=40, fp16 logits, fp32 accum) + bias + log_softmax
// ===========================================================================
__global__ void __launch_bounds__(256) spmm_csr40_lsm(
    const __half* __restrict__ C, const int* __restrict__ rp,
    const uint32_t* __restrict__ pe, const float* __restrict__ b,
    float* __restrict__ out, int M) {
    int row = blockIdx.x * 8 + (threadIdx.x >> 5);
    int lane = threadIdx.x & 31;
    if (row >= M) return;
    int p  = __ldg(rp + row);
    int pend = __ldg(rp + row + 1);

    float a0 = 0.f, a1 = 0.f;
    for (; p + 2 <= pend; p += 2) {
        int s0, s1;
        float w0, w1;
        unpack_edge(__ldg(pe + p), s0, w0);
        unpack_edge(__ldg(pe + p + 1), s1, w1);
        const __half* c0 = C + (size_t)s0 * 40;
        const __half* c1 = C + (size_t)s1 * 40;
        float x0 = __half2float(__ldg(c0 + lane));
        float x1 = __half2float(__ldg(c1 + lane));
        float y0 = (lane < 8) ? __half2float(__ldg(c0 + 32 + lane)) : 0.f;
        float y1 = (lane < 8) ? __half2float(__ldg(c1 + 32 + lane)) : 0.f;
        a0 = fmaf(w0, x0, a0); a0 = fmaf(w1, x1, a0);
        a1 = fmaf(w0, y0, a1); a1 = fmaf(w1, y1, a1);
    }
    if (p < pend) {
        int s;
        float w;
        unpack_edge(__ldg(pe + p), s, w);
        const __half* c0 = C + (size_t)s * 40;
        a0 = fmaf(w, __half2float(__ldg(c0 + lane)), a0);
        if (lane < 8) a1 = fmaf(w, __half2float(__ldg(c0 + 32 + lane)), a1);
    }

    float v0 = a0 + __ldg(b + lane);
    float v1 = (lane < 8) ? (a1 + __ldg(b + 32 + lane)) : -INFINITY;

    float m = fmaxf(v0, v1);
#pragma unroll
    for (int o = 16; o > 0; o >>= 1) m = fmaxf(m, __shfl_xor_sync(0xffffffffu, m, o));
    float s = __expf(v0 - m) + ((lane < 8) ? __expf(v1 - m) : 0.f);
#pragma unroll
    for (int o = 16; o > 0; o >>= 1) s += __shfl_xor_sync(0xffffffffu, s, o);
    float ls = m + __logf(s);

    out[(size_t)row * 40 + lane] = v0 - ls;
    if (lane < 8) out[(size_t)row * 40 + 32 + lane] = v1 - ls;
}

// ===========================================================================
extern "C" void kernel_launch(void* const* d_in, const int* in_sizes, int n_in,
                              void* d_out, int out_size) {
    const float* x    = (const float*)d_in[0];
    const int*   esrc = (const int*)  d_in[1];
    const int*   edst = (const int*)  d_in[2];
    const float* ew   = (const float*)d_in[3];
    const float* W1   = (const float*)d_in[4];
    const float* b1   = (const float*)d_in[5];
    const float* Wh   = (const float*)d_in[6];
    const float* bh   = (const float*)d_in[7];
    const float* W2   = (const float*)d_in[8];
    const float* b2   = (const float*)d_in[9];
    float* out = (float*)d_out;

    const int M  = in_sizes[0] / NFEAT;   // 50000
    const int nE = in_sizes[1];           // 1600000

    __half *Ah, *Bh, *Ch;
    int *cnt, *cursor, *rp, *tmp, *bsum;
    uint32_t *pe;
    uint32_t *W1h, *W1l, *Whh, *Whl;
    cudaGetSymbolAddress((void**)&Ah, g_Ah);
    cudaGetSymbolAddress((void**)&Bh, g_Bh);
    cudaGetSymbolAddress((void**)&Ch, g_Ch);
    cudaGetSymbolAddress((void**)&cnt, g_cnt);
    cudaGetSymbolAddress((void**)&cursor, g_cursor);
    cudaGetSymbolAddress((void**)&rp, g_rp);
    cudaGetSymbolAddress((void**)&tmp, g_tmp);
    cudaGetSymbolAddress((void**)&bsum, g_bsum);
    cudaGetSymbolAddress((void**)&pe, g_pe);
    cudaGetSymbolAddress((void**)&W1h, g_W1h);
    cudaGetSymbolAddress((void**)&W1l, g_W1l);
    cudaGetSymbolAddress((void**)&Whh, g_Whh);
    cudaGetSymbolAddress((void**)&Whl, g_Whl);

    static cudaStream_t s2 = nullptr;
    static cudaEvent_t evF = nullptr, evJ = nullptr;
    if (!s2) {
        cudaStreamCreateWithFlags(&s2, cudaStreamNonBlocking);
        cudaEventCreateWithFlags(&evF, cudaEventDisableTiming);
        cudaEventCreateWithFlags(&evJ, cudaEventDisableTiming);
        cudaFuncSetAttribute(mma_gemm128<float>,
                             cudaFuncAttributeMaxDynamicSharedMemorySize, SM_U32 * 4);
        cudaFuncSetAttribute(mma_gemm128<__half>,
                             cudaFuncAttributeMaxDynamicSharedMemorySize, SM_U32 * 4);
    }

    const int nb = (M + 255) / 256;           // 196
    const int gemmBlocks = (M + 127) / 128;   // 391
    const int spmmBlocks = (M + 7) / 8;
    const int nE4 = (nE + 3) / 4;

    // ---- Fork: CSR build on s2, weight pack + layer-1 GEMM on main ----
    cudaEventRecord(evF, 0);
    cudaStreamWaitEvent(s2, evF, 0);

    zero_int4<<<(M / 4 + 255) / 256, 256, 0, s2>>>((int4*)cnt, (M + 3) / 4);
    hist_dst4<<<((nE / 4) + 255) / 256, 256, 0, s2>>>((const int4*)edst, cnt, nE / 4);
    scan_p1<<<nb, 256, 0, s2>>>(cnt, tmp, bsum, M);
    scan_p3<<<nb, 256, 0, s2>>>(tmp, bsum, rp, cursor, M, nb, nE);
    scatter_edges4<<<(nE4 + 255) / 256, 256, 0, s2>>>(esrc, edst, ew, cursor, pe, nE);
    cudaEventRecord(evJ, s2);

    conv_weights<<<160, 256>>>(W1, Wh, W1h, W1l, Whh, Whl);
    mma_gemm128<float><<<gemmBlocks, 256, SM_U32 * 4>>>(x, W1h, W1l, Ah, M, NFEAT);

    cudaStreamWaitEvent(0, evJ, 0);   // join

    // Layer 1 aggregation (fp16 out)
    spmm_csr128h<<<spmmBlocks, 256>>>(Ah, rp, pe, b1, Bh, M);

    // Layer 2 (fp16 in)
    mma_gemm128<__half><<<gemmBlocks, 256, SM_U32 * 4>>>(Bh, Whh, Whl, Ah, M, NHID);
    spmm_csr128h<<<spmmBlocks, 256>>>(Ah, rp, pe, bh, Bh, M);

    // Layer 3 + log_softmax
    sgemm40<<<(M + 31) / 32, 256>>>(Bh, W2, Ch, M);
    spmm_csr40_lsm<<<spmmBlocks, 256>>>(Ch, rp, pe, b2, out, M);
}